// round 13
// baseline (speedup 1.0000x reference)
#include <cuda_runtime.h>
#include <cuda_bf16.h>
#include <cstdint>

// GroupQueryAttention: B=2, S=2048, E=768, H=12, G=4, D=64, T=512
// Round 13: fix attention register-spill hypothesis. attn_mma moves to
// 128-thread CTAs with __launch_bounds__(128,2) -> 256-reg cap (was 128,
// forcing hot-loop spills at ~150 live regs). exp -> exp2 with log2(e)
// folded into the upstream q prescale. GEMM (ldsm) and cvt as round 12.

constexpr int kE = 768;
constexpr int kB = 2;
constexpr int kS = 2048;
constexpr int kH = 12;
constexpr int kG = 4;
constexpr int kD = 64;
constexpr int kT = 512;                 // S / G
constexpr int kNSE = kB * kS * kE;      // 3,145,728
constexpr int kEE  = kE * kE;           // 589,824
constexpr int kGEE = kG * kE * kE;      // 2,359,296
constexpr int kGSE = kB * kG * kS * kE; // 12,582,912
constexpr int kQTE = kB * kG * kT * kE; // 3,145,728

// ---------------- scratch (device globals; no allocations allowed) ----------
__device__ __nv_bfloat16 c_q_h[kNSE], c_q_l[kNSE];
__device__ __nv_bfloat16 c_k_h[kNSE], c_k_l[kNSE];
__device__ __nv_bfloat16 c_v_h[kNSE], c_v_l[kNSE];
__device__ __nv_bfloat16 a_q_h[kNSE], a_q_l[kNSE];
__device__ __nv_bfloat16 a_k_h[kNSE], a_k_l[kNSE];
__device__ __nv_bfloat16 a_x_h[kNSE], a_x_l[kNSE];
__device__ __nv_bfloat16 a_qi_h[kQTE], a_qi_l[kQTE];
__device__ __nv_bfloat16 a_ki_h[kGSE], a_ki_l[kGSE];
__device__ __nv_bfloat16 a_vi_h[kGSE], a_vi_l[kGSE];
__device__ __nv_bfloat16 a_c_h[kQTE], a_c_l[kQTE];
__device__ __nv_bfloat16 w0_h[kEE],  w0_l[kEE];
__device__ __nv_bfloat16 w1_h[kEE],  w1_l[kEE];
__device__ __nv_bfloat16 w2_h[kEE],  w2_l[kEE];
__device__ __nv_bfloat16 wq_h[kGEE], wq_l[kGEE];
__device__ __nv_bfloat16 wk_h[kGEE], wk_l[kGEE];
__device__ __nv_bfloat16 wv_h[kGEE], wv_l[kGEE];
__device__ __nv_bfloat16 wo_h[kGEE], wo_l[kGEE];

// ---------------- helpers ----------------------------------------------------
__device__ __forceinline__ uint32_t smem_u32(const void* p) {
    uint32_t a;
    asm("{ .reg .u64 t; cvta.to.shared.u64 t, %1; cvt.u32.u64 %0, t; }"
        : "=r"(a) : "l"(p));
    return a;
}
__device__ __forceinline__ void cp16(uint32_t dst, const void* src) {
    asm volatile("cp.async.cg.shared.global [%0], [%1], 16;" :: "r"(dst), "l"(src));
}
#define CP_COMMIT() asm volatile("cp.async.commit_group;" ::: "memory")
#define CP_WAIT0()  asm volatile("cp.async.wait_group 0;" ::: "memory")

__device__ __forceinline__ void mma_bf16(float* c, const uint32_t* a, const uint32_t* b) {
    asm volatile(
        "mma.sync.aligned.m16n8k16.row.col.f32.bf16.bf16.f32 "
        "{%0,%1,%2,%3}, {%4,%5,%6,%7}, {%8,%9}, {%0,%1,%2,%3};"
        : "+f"(c[0]), "+f"(c[1]), "+f"(c[2]), "+f"(c[3])
        : "r"(a[0]), "r"(a[1]), "r"(a[2]), "r"(a[3]), "r"(b[0]), "r"(b[1]));
}
__device__ __forceinline__ void ldsm4(uint32_t& r0, uint32_t& r1, uint32_t& r2,
                                      uint32_t& r3, uint32_t addr) {
    asm volatile("ldmatrix.sync.aligned.m8n8.x4.shared.b16 {%0,%1,%2,%3}, [%4];"
                 : "=r"(r0), "=r"(r1), "=r"(r2), "=r"(r3) : "r"(addr));
}
__device__ __forceinline__ void ldsm4t(uint32_t& r0, uint32_t& r1, uint32_t& r2,
                                       uint32_t& r3, uint32_t addr) {
    asm volatile("ldmatrix.sync.aligned.m8n8.x4.trans.shared.b16 {%0,%1,%2,%3}, [%4];"
                 : "=r"(r0), "=r"(r1), "=r"(r2), "=r"(r3) : "r"(addr));
}

__device__ __forceinline__ void split1(float x, __nv_bfloat16& h, __nv_bfloat16& l) {
    h = __float2bfloat16(x);
    l = __float2bfloat16(x - __bfloat162float(h));
}
__device__ __forceinline__ uint32_t pk(__nv_bfloat16 a, __nv_bfloat16 b) {
    uint16_t ua = *(uint16_t*)&a, ub = *(uint16_t*)&b;
    return (uint32_t)ua | ((uint32_t)ub << 16);
}

// ---------------- row mappings -----------------------------------------------
template <int MODE>
__device__ __forceinline__ int in_row(int m) {
    if (MODE == 1) {
        int b = m >> 11; int g = (m >> 9) & 3; int t = m & 511;
        return (b << 11) + (t << 2) + g;
    }
    if (MODE == 2) {
        int b = m >> 13; int s = m & 2047;
        return (b << 11) + s;
    }
    return m;
}
__device__ __forceinline__ int perm_row(int m) {
    int b = m >> 11; int g = (m >> 9) & 3; int t = m & 511;
    return (b << 11) + (t << 2) + g;
}

// ---------------- hi/lo conversion kernels -----------------------------------
__device__ __forceinline__ void cvt_one(const float4* in, uint2* h, uint2* l, int i) {
    float4 v = in[i];
    __nv_bfloat16 h0, l0, h1, l1, h2, l2, h3, l3;
    split1(v.x, h0, l0); split1(v.y, h1, l1);
    split1(v.z, h2, l2); split1(v.w, h3, l3);
    h[i] = make_uint2(pk(h0, h1), pk(h2, h3));
    l[i] = make_uint2(pk(l0, l1), pk(l2, l3));
}
__global__ void cvt_hl(const float4* __restrict__ in, uint2* __restrict__ h,
                       uint2* __restrict__ l, int n4) {
    int i = blockIdx.x * 256 + threadIdx.x;
    if (i < n4) cvt_one(in, h, l, i);
}
__global__ void cvt_hl3(const float4* __restrict__ i0, uint2* __restrict__ h0, uint2* __restrict__ l0,
                        const float4* __restrict__ i1, uint2* __restrict__ h1, uint2* __restrict__ l1,
                        const float4* __restrict__ i2, uint2* __restrict__ h2, uint2* __restrict__ l2,
                        int n4) {
    int i = blockIdx.x * 256 + threadIdx.x;
    if (i >= n4) return;
    if (blockIdx.y == 0)      cvt_one(i0, h0, l0, i);
    else if (blockIdx.y == 1) cvt_one(i1, h1, l1, i);
    else                      cvt_one(i2, h2, l2, i);
}

// ---------------- bf16x3 HMMA GEMM (ldmatrix fragments) ----------------------
constexpr int PSTR = 40;               // padded row stride (bf16 elems)
constexpr int MATB = 128 * PSTR * 2;   // 10240 B per matrix
constexpr int BUFB = 4 * MATB;         // 40960 B per buffer (Ah|Al|Wh|Wl)
constexpr int kSmemGemm = 2 * BUFB;    // 81920 B

template <int MODE, int OUT>   // OUT: 0 = fp32, 1 = bf16 hi/lo (scaled)
__global__ __launch_bounds__(256, 2)
void gemm_mma(const __nv_bfloat16* __restrict__ Ah, const __nv_bfloat16* __restrict__ Al,
              const __nv_bfloat16* __restrict__ Wh, const __nv_bfloat16* __restrict__ Wl,
              const float* __restrict__ bias, float* __restrict__ outF,
              __nv_bfloat16* __restrict__ outH, __nv_bfloat16* __restrict__ outL,
              float scale) {
    extern __shared__ char s_raw[];
    const uint32_t sb = smem_u32(s_raw);

    const int tid = threadIdx.x;
    const int m0 = blockIdx.y * 128;
    const int n0 = blockIdx.x * 128;

    int g = 0;
    if (MODE == 1 || MODE == 3) g = (m0 >> 9) & 3;
    if (MODE == 2)              g = (m0 >> 11) & 3;
    const __nv_bfloat16* WgH = Wh + (size_t)g * kEE;
    const __nv_bfloat16* WgL = Wl + (size_t)g * kEE;
    const float* bg = bias + (size_t)g * kE;

    const int lrow = tid >> 1;
    const int lhalf = tid & 1;
    const int arow = in_row<MODE>(m0 + lrow);
    const __nv_bfloat16* pAh = Ah  + (size_t)arow * kE + lhalf * 16;
    const __nv_bfloat16* pAl = Al  + (size_t)arow * kE + lhalf * 16;
    const __nv_bfloat16* pWh = WgH + (size_t)(n0 + lrow) * kE + lhalf * 16;
    const __nv_bfloat16* pWl = WgL + (size_t)(n0 + lrow) * kE + lhalf * 16;
    const uint32_t sdst = sb + (uint32_t)(lrow * PSTR + lhalf * 16) * 2;

    const int lane = tid & 31;
    const int wid = tid >> 5;
    const int r0 = (wid & 3) * 32;
    const int c0 = (wid >> 2) * 64;
    const int lr = lane >> 2;
    const int lq = lane & 3;

    const uint32_t lmo = (uint32_t)((lane & 15) * PSTR + (lane >> 4) * 8) * 2;

    float acc[2][8][4];
#pragma unroll
    for (int i = 0; i < 2; i++)
#pragma unroll
        for (int j = 0; j < 8; j++)
#pragma unroll
            for (int q = 0; q < 4; q++) acc[i][j][q] = 0.f;

    {
        cp16(sdst,            pAh); cp16(sdst + 16,            pAh + 8);
        cp16(sdst + MATB,     pAl); cp16(sdst + MATB + 16,     pAl + 8);
        cp16(sdst + 2 * MATB, pWh); cp16(sdst + 2 * MATB + 16, pWh + 8);
        cp16(sdst + 3 * MATB, pWl); cp16(sdst + 3 * MATB + 16, pWl + 8);
        CP_COMMIT();
    }

#pragma unroll 1
    for (int p = 0; p < 24; ++p) {
        CP_WAIT0();
        __syncthreads();
        if (p + 1 < 24) {
            const int go = (p + 1) * 32;
            const uint32_t d = sdst + ((p + 1) & 1) * BUFB;
            cp16(d,            pAh + go); cp16(d + 16,            pAh + go + 8);
            cp16(d + MATB,     pAl + go); cp16(d + MATB + 16,     pAl + go + 8);
            cp16(d + 2 * MATB, pWh + go); cp16(d + 2 * MATB + 16, pWh + go + 8);
            cp16(d + 3 * MATB, pWl + go); cp16(d + 3 * MATB + 16, pWl + go + 8);
            CP_COMMIT();
        }

        const uint32_t bbase = sb + (p & 1) * BUFB;
#pragma unroll
        for (int ks = 0; ks < 2; ++ks) {
            const uint32_t ko = lmo + (uint32_t)(ks * 16) * 2;
            uint32_t AhF[2][4], AlF[2][4], BF[8][2];
#pragma unroll
            for (int i = 0; i < 2; i++) {
                const uint32_t ab = bbase + (uint32_t)((r0 + i * 16) * PSTR) * 2 + ko;
                ldsm4(AhF[i][0], AhF[i][1], AhF[i][2], AhF[i][3], ab);
                ldsm4(AlF[i][0], AlF[i][1], AlF[i][2], AlF[i][3], ab + MATB);
            }
#pragma unroll
            for (int u = 0; u < 4; u++) {
                uint32_t q0, q1, q2, q3;
                ldsm4(q0, q1, q2, q3,
                      bbase + 2 * MATB + (uint32_t)((c0 + u * 16) * PSTR) * 2 + ko);
                BF[2 * u][0] = q0; BF[2 * u][1] = q2;
                BF[2 * u + 1][0] = q1; BF[2 * u + 1][1] = q3;
            }
#pragma unroll
            for (int j = 0; j < 8; j++) {
                mma_bf16(acc[0][j], AhF[0], BF[j]);
                mma_bf16(acc[1][j], AhF[1], BF[j]);
            }
#pragma unroll
            for (int j = 0; j < 8; j++) {
                mma_bf16(acc[0][j], AlF[0], BF[j]);
                mma_bf16(acc[1][j], AlF[1], BF[j]);
            }
#pragma unroll
            for (int u = 0; u < 4; u++) {
                uint32_t q0, q1, q2, q3;
                ldsm4(q0, q1, q2, q3,
                      bbase + 3 * MATB + (uint32_t)((c0 + u * 16) * PSTR) * 2 + ko);
                BF[2 * u][0] = q0; BF[2 * u][1] = q2;
                BF[2 * u + 1][0] = q1; BF[2 * u + 1][1] = q3;
            }
#pragma unroll
            for (int j = 0; j < 8; j++) {
                mma_bf16(acc[0][j], AhF[0], BF[j]);
                mma_bf16(acc[1][j], AhF[1], BF[j]);
            }
        }
    }

#pragma unroll
    for (int i = 0; i < 2; i++) {
#pragma unroll
        for (int half = 0; half < 2; half++) {
            const int m = m0 + r0 + i * 16 + lr + half * 8;
            const size_t orow = (MODE == 3) ? (size_t)perm_row(m) : (size_t)m;
#pragma unroll
            for (int j = 0; j < 8; j++) {
                const int col = n0 + c0 + j * 8 + lq * 2;
                const float2 bb = *(const float2*)(bg + col);
                float x0 = acc[i][j][half * 2 + 0] + bb.x;
                float x1 = acc[i][j][half * 2 + 1] + bb.y;
                if (OUT == 1) {
                    x0 *= scale; x1 *= scale;
                    __nv_bfloat16 h0, l0, h1, l1;
                    split1(x0, h0, l0); split1(x1, h1, l1);
                    *(uint32_t*)(outH + orow * kE + col) = pk(h0, h1);
                    *(uint32_t*)(outL + orow * kE + col) = pk(l0, l1);
                } else {
                    *(float2*)(outF + orow * kE + col) = make_float2(x0, x1);
                }
            }
        }
    }
}

// ---------------- HMMA flash attention (128 threads, 256-reg budget) ---------
// grid (T/64, B*G*H), 128 threads (4 warps). Warp w: q rows q0 + w*16 .. +15.
// BKV=64. Same math as round 10 but scores are in base-2 domain (log2e folded
// into the upstream q prescale) -> exp2f everywhere.
constexpr int ASTR = 72;   // smem row stride in bf16 elems

__global__ __launch_bounds__(128, 2)
void attn_mma() {
    __shared__ __align__(16) uint16_t sKh[64 * ASTR], sKl[64 * ASTR];
    __shared__ __align__(16) uint16_t sVh[64 * ASTR], sVl[64 * ASTR];

    const int tid = threadIdx.x;
    const int wid = tid >> 5;
    const int lane = tid & 31;
    const int lr = lane >> 2;
    const int lq = lane & 3;

    const int y = blockIdx.y;
    const int b = y / (kG * kH);
    const int g = (y / kH) & 3;
    const int h = y % kH;
    const int q0 = blockIdx.x * 64;

    const size_t head_q  = ((size_t)(b * kG + g) * kT) * kE + h * kD;
    const size_t head_kv = ((size_t)(b * kG + g) * kS) * kE + h * kD;

    // Q fragments (held in registers for the whole kernel); q pre-scaled by
    // 0.125*log2(e) upstream -> scores in base-2 domain.
    uint32_t qh[4][4], ql[4][4];
    {
        const size_t r0o = head_q + (size_t)(q0 + wid * 16 + lr) * kE;
        const size_t r1o = r0o + 8 * kE;
#pragma unroll
        for (int kc = 0; kc < 4; kc++) {
            const int cA = kc * 16 + lq * 2;
            qh[kc][0] = *(const uint32_t*)(a_qi_h + r0o + cA);
            qh[kc][1] = *(const uint32_t*)(a_qi_h + r1o + cA);
            qh[kc][2] = *(const uint32_t*)(a_qi_h + r0o + cA + 8);
            qh[kc][3] = *(const uint32_t*)(a_qi_h + r1o + cA + 8);
            ql[kc][0] = *(const uint32_t*)(a_qi_l + r0o + cA);
            ql[kc][1] = *(const uint32_t*)(a_qi_l + r1o + cA);
            ql[kc][2] = *(const uint32_t*)(a_qi_l + r0o + cA + 8);
            ql[kc][3] = *(const uint32_t*)(a_qi_l + r1o + cA + 8);
        }
    }

    const uint32_t lko = (uint32_t)((((lane >> 3) & 1) * 8 + (lane & 7)) * ASTR * 2
                                    + (lane >> 4) * 16);
    const uint32_t bKh = smem_u32(sKh), bKl = smem_u32(sKl);
    const uint32_t bVh = smem_u32(sVh), bVl = smem_u32(sVl);

    float o[8][4];
#pragma unroll
    for (int j = 0; j < 8; j++)
#pragma unroll
        for (int e = 0; e < 4; e++) o[j][e] = 0.f;
    float m0 = -1e30f, m1 = -1e30f, l0 = 0.f, l1 = 0.f;

    // tile-load addressing: 128 threads, 2 per row, 32-col halves
    const int trow = tid >> 1;
    const int tcol = (tid & 1) * 32;
    const uint32_t sof = (uint32_t)(trow * ASTR + tcol) * 2;

#pragma unroll 1
    for (int kv = 0; kv < kS; kv += 64) {
        {
            const size_t gofs = head_kv + (size_t)(kv + trow) * kE + tcol;
#pragma unroll
            for (int c = 0; c < 4; c++) {
                *(uint4*)((char*)sKh + sof + c * 16) = *(const uint4*)(a_ki_h + gofs + c * 8);
                *(uint4*)((char*)sKl + sof + c * 16) = *(const uint4*)(a_ki_l + gofs + c * 8);
                *(uint4*)((char*)sVh + sof + c * 16) = *(const uint4*)(a_vi_h + gofs + c * 8);
                *(uint4*)((char*)sVl + sof + c * 16) = *(const uint4*)(a_vi_l + gofs + c * 8);
            }
        }
        __syncthreads();

        // ---- QK ----
        float acc[8][4];
#pragma unroll
        for (int j = 0; j < 8; j++)
#pragma unroll
            for (int e = 0; e < 4; e++) acc[j][e] = 0.f;

#pragma unroll
        for (int kc = 0; kc < 4; kc++) {
            uint32_t kb[8][2];
#pragma unroll
            for (int u = 0; u < 4; u++) {
                uint32_t r0, r1, r2, r3;
                ldsm4(r0, r1, r2, r3, bKh + (uint32_t)(u * 16 * ASTR + kc * 16) * 2 + lko);
                kb[2 * u][0] = r0; kb[2 * u][1] = r2;
                kb[2 * u + 1][0] = r1; kb[2 * u + 1][1] = r3;
            }
#pragma unroll
            for (int j = 0; j < 8; j++) mma_bf16(acc[j], qh[kc], kb[j]);
#pragma unroll
            for (int j = 0; j < 8; j++) mma_bf16(acc[j], ql[kc], kb[j]);
#pragma unroll
            for (int u = 0; u < 4; u++) {
                uint32_t r0, r1, r2, r3;
                ldsm4(r0, r1, r2, r3, bKl + (uint32_t)(u * 16 * ASTR + kc * 16) * 2 + lko);
                kb[2 * u][0] = r0; kb[2 * u][1] = r2;
                kb[2 * u + 1][0] = r1; kb[2 * u + 1][1] = r3;
            }
#pragma unroll
            for (int j = 0; j < 8; j++) mma_bf16(acc[j], qh[kc], kb[j]);
        }

        // ---- online softmax (base-2) ----
        float mt0 = -1e30f, mt1 = -1e30f;
#pragma unroll
        for (int j = 0; j < 8; j++) {
            mt0 = fmaxf(mt0, fmaxf(acc[j][0], acc[j][1]));
            mt1 = fmaxf(mt1, fmaxf(acc[j][2], acc[j][3]));
        }
        mt0 = fmaxf(mt0, __shfl_xor_sync(0xffffffffu, mt0, 1));
        mt0 = fmaxf(mt0, __shfl_xor_sync(0xffffffffu, mt0, 2));
        mt1 = fmaxf(mt1, __shfl_xor_sync(0xffffffffu, mt1, 1));
        mt1 = fmaxf(mt1, __shfl_xor_sync(0xffffffffu, mt1, 2));
        const float mn0 = fmaxf(m0, mt0);
        const float mn1 = fmaxf(m1, mt1);
        const float cr0 = exp2f(m0 - mn0);
        const float cr1 = exp2f(m1 - mn1);
        m0 = mn0; m1 = mn1;
        l0 *= cr0; l1 *= cr1;
#pragma unroll
        for (int j = 0; j < 8; j++) {
            o[j][0] *= cr0; o[j][1] *= cr0;
            o[j][2] *= cr1; o[j][3] *= cr1;
        }

        uint32_t pha[4][4], pla[4][4];
#pragma unroll
        for (int j = 0; j < 8; j++) {
            const float p0 = exp2f(acc[j][0] - m0);
            const float p1 = exp2f(acc[j][1] - m0);
            const float p2 = exp2f(acc[j][2] - m1);
            const float p3 = exp2f(acc[j][3] - m1);
            l0 += p0 + p1; l1 += p2 + p3;
            __nv_bfloat16 h0, e0, h1, e1, h2, e2, h3, e3;
            split1(p0, h0, e0); split1(p1, h1, e1);
            split1(p2, h2, e2); split1(p3, h3, e3);
            const int sc = j >> 1, hh = (j & 1) * 2;
            pha[sc][hh + 0] = pk(h0, h1); pha[sc][hh + 1] = pk(h2, h3);
            pla[sc][hh + 0] = pk(e0, e1); pla[sc][hh + 1] = pk(e2, e3);
        }

        // ---- PV ----
#pragma unroll
        for (int sc = 0; sc < 4; sc++) {
            uint32_t vb[8][2];
#pragma unroll
            for (int u = 0; u < 4; u++) {
                uint32_t r0, r1, r2, r3;
                ldsm4t(r0, r1, r2, r3, bVh + (uint32_t)(sc * 16 * ASTR + u * 16) * 2 + lko);
                vb[2 * u][0] = r0; vb[2 * u][1] = r1;
                vb[2 * u + 1][0] = r2; vb[2 * u + 1][1] = r3;
            }
#pragma unroll
            for (int j = 0; j < 8; j++) mma_bf16(o[j], pha[sc], vb[j]);
#pragma unroll
            for (int j = 0; j < 8; j++) mma_bf16(o[j], pla[sc], vb[j]);
#pragma unroll
            for (int u = 0; u < 4; u++) {
                uint32_t r0, r1, r2, r3;
                ldsm4t(r0, r1, r2, r3, bVl + (uint32_t)(sc * 16 * ASTR + u * 16) * 2 + lko);
                vb[2 * u][0] = r0; vb[2 * u][1] = r1;
                vb[2 * u + 1][0] = r2; vb[2 * u + 1][1] = r3;
            }
#pragma unroll
            for (int j = 0; j < 8; j++) mma_bf16(o[j], pha[sc], vb[j]);
        }
        __syncthreads();
    }

    // ---- epilogue ----
    l0 += __shfl_xor_sync(0xffffffffu, l0, 1);
    l0 += __shfl_xor_sync(0xffffffffu, l0, 2);
    l1 += __shfl_xor_sync(0xffffffffu, l1, 1);
    l1 += __shfl_xor_sync(0xffffffffu, l1, 2);
    const float inv0 = 1.0f / l0, inv1 = 1.0f / l1;
    const size_t r0o = head_q + (size_t)(q0 + wid * 16 + lr) * kE;
    const size_t r1o = r0o + 8 * kE;
#pragma unroll
    for (int j = 0; j < 8; j++) {
        const int col = j * 8 + lq * 2;
        __nv_bfloat16 h0, e0, h1, e1;
        split1(o[j][0] * inv0, h0, e0); split1(o[j][1] * inv0, h1, e1);
        *(uint32_t*)(a_c_h + r0o + col) = pk(h0, h1);
        *(uint32_t*)(a_c_l + r0o + col) = pk(e0, e1);
        split1(o[j][2] * inv1, h0, e0); split1(o[j][3] * inv1, h1, e1);
        *(uint32_t*)(a_c_h + r1o + col) = pk(h0, h1);
        *(uint32_t*)(a_c_l + r1o + col) = pk(e0, e1);
    }
}

// ---------------- launch ----------------------------------------------------
extern "C" void kernel_launch(void* const* d_in, const int* in_sizes, int n_in,
                              void* d_out, int out_size) {
    const float* query = (const float*)d_in[0];
    const float* key   = (const float*)d_in[1];
    const float* value = (const float*)d_in[2];
    const float* Wqg   = (const float*)d_in[3];
    const float* bqg   = (const float*)d_in[4];
    const float* Wk    = (const float*)d_in[5];
    const float* bk    = (const float*)d_in[6];
    const float* Wv    = (const float*)d_in[7];
    const float* bv    = (const float*)d_in[8];
    const float* Wq_in = (const float*)d_in[9];
    const float* bq_in = (const float*)d_in[10];
    const float* Wk_in = (const float*)d_in[11];
    const float* bk_in = (const float*)d_in[12];
    const float* Wv_in = (const float*)d_in[13];
    const float* bv_in = (const float*)d_in[14];
    const float* Wout  = (const float*)d_in[15];
    const float* bout  = (const float*)d_in[16];

#define SYM(p, s) void* p; cudaGetSymbolAddress(&p, s)
    SYM(p_cq_h, c_q_h); SYM(p_cq_l, c_q_l);
    SYM(p_ck_h, c_k_h); SYM(p_ck_l, c_k_l);
    SYM(p_cv_h, c_v_h); SYM(p_cv_l, c_v_l);
    SYM(p_aq_h, a_q_h); SYM(p_aq_l, a_q_l);
    SYM(p_ak_h, a_k_h); SYM(p_ak_l, a_k_l);
    SYM(p_ax_h, a_x_h); SYM(p_ax_l, a_x_l);
    SYM(p_qi_h, a_qi_h); SYM(p_qi_l, a_qi_l);
    SYM(p_ki_h, a_ki_h); SYM(p_ki_l, a_ki_l);
    SYM(p_vi_h, a_vi_h); SYM(p_vi_l, a_vi_l);
    SYM(p_ac_h, a_c_h); SYM(p_ac_l, a_c_l);
    SYM(p_w0_h, w0_h);  SYM(p_w0_l, w0_l);
    SYM(p_w1_h, w1_h);  SYM(p_w1_l, w1_l);
    SYM(p_w2_h, w2_h);  SYM(p_w2_l, w2_l);
    SYM(p_wq_h, wq_h);  SYM(p_wq_l, wq_l);
    SYM(p_wk_h, wk_h);  SYM(p_wk_l, wk_l);
    SYM(p_wv_h, wv_h);  SYM(p_wv_l, wv_l);
    SYM(p_wo_h, wo_h);  SYM(p_wo_l, wo_l);
#undef SYM

    cudaFuncSetAttribute(gemm_mma<0, 1>, cudaFuncAttributeMaxDynamicSharedMemorySize, kSmemGemm);
    cudaFuncSetAttribute(gemm_mma<1, 1>, cudaFuncAttributeMaxDynamicSharedMemorySize, kSmemGemm);
    cudaFuncSetAttribute(gemm_mma<2, 1>, cudaFuncAttributeMaxDynamicSharedMemorySize, kSmemGemm);
    cudaFuncSetAttribute(gemm_mma<3, 0>, cudaFuncAttributeMaxDynamicSharedMemorySize, kSmemGemm);

    typedef const __nv_bfloat16* BP;
    typedef __nv_bfloat16* BPm;
    typedef const float4* F4;
    typedef uint2* U2;

    // hi/lo conversions: 4 batched launches
    cvt_hl3<<<dim3(kNSE / 4 / 256, 3), 256>>>(
        (F4)query, (U2)p_cq_h, (U2)p_cq_l,
        (F4)key,   (U2)p_ck_h, (U2)p_ck_l,
        (F4)value, (U2)p_cv_h, (U2)p_cv_l, kNSE / 4);
    cvt_hl3<<<dim3(kEE / 4 / 256, 3), 256>>>(
        (F4)Wqg, (U2)p_w0_h, (U2)p_w0_l,
        (F4)Wk,  (U2)p_w1_h, (U2)p_w1_l,
        (F4)Wv,  (U2)p_w2_h, (U2)p_w2_l, kEE / 4);
    cvt_hl3<<<dim3(kGEE / 4 / 256, 3), 256>>>(
        (F4)Wq_in, (U2)p_wq_h, (U2)p_wq_l,
        (F4)Wk_in, (U2)p_wk_h, (U2)p_wk_l,
        (F4)Wv_in, (U2)p_wv_h, (U2)p_wv_l, kGEE / 4);
    cvt_hl<<<kGEE / 4 / 256, 256>>>((F4)Wout, (U2)p_wo_h, (U2)p_wo_l, kGEE / 4);

    const dim3 blk(256);
    gemm_mma<0, 1><<<dim3(6, 32), blk, kSmemGemm>>>(
        (BP)p_cq_h, (BP)p_cq_l, (BP)p_w0_h, (BP)p_w0_l, bqg,
        nullptr, (BPm)p_aq_h, (BPm)p_aq_l, 1.0f);
    gemm_mma<0, 1><<<dim3(6, 32), blk, kSmemGemm>>>(
        (BP)p_ck_h, (BP)p_ck_l, (BP)p_w1_h, (BP)p_w1_l, bk,
        nullptr, (BPm)p_ak_h, (BPm)p_ak_l, 1.0f);
    gemm_mma<0, 1><<<dim3(6, 32), blk, kSmemGemm>>>(
        (BP)p_cv_h, (BP)p_cv_l, (BP)p_w2_h, (BP)p_w2_l, bv,
        nullptr, (BPm)p_ax_h, (BPm)p_ax_l, 1.0f);
    // q in-proj prescaled by 1/sqrt(D) * log2(e) -> base-2 softmax downstream
    gemm_mma<1, 1><<<dim3(6, 32), blk, kSmemGemm>>>(
        (BP)p_aq_h, (BP)p_aq_l, (BP)p_wq_h, (BP)p_wq_l, bq_in,
        nullptr, (BPm)p_qi_h, (BPm)p_qi_l, 0.125f * 1.44269504f);
    gemm_mma<2, 1><<<dim3(6, 128), blk, kSmemGemm>>>(
        (BP)p_ak_h, (BP)p_ak_l, (BP)p_wk_h, (BP)p_wk_l, bk_in,
        nullptr, (BPm)p_ki_h, (BPm)p_ki_l, 1.0f);
    gemm_mma<2, 1><<<dim3(6, 128), blk, kSmemGemm>>>(
        (BP)p_ax_h, (BP)p_ax_l, (BP)p_wv_h, (BP)p_wv_l, bv_in,
        nullptr, (BPm)p_vi_h, (BPm)p_vi_l, 1.0f);
    attn_mma<<<dim3(kT / 64, kB * kG * kH), dim3(128)>>>();
    gemm_mma<3, 0><<<dim3(6, 32), blk, kSmemGemm>>>(
        (BP)p_ac_h, (BP)p_ac_l, (BP)p_wo_h, (BP)p_wo_l, bout,
        (float*)d_out, nullptr, nullptr, 1.0f);
}

// round 14
// speedup vs baseline: 1.1853x; 1.1853x over previous
#include <cuda_runtime.h>
#include <cuda_bf16.h>
#include <cstdint>

// GroupQueryAttention: B=2, S=2048, E=768, H=12, G=4, D=64, T=512
// Round 14: launch-merge. 7 GEMM launches -> 3 via runtime job table
// (fixes CTA-count imbalance: 192-CTA launches on 296 co-residency slots).
// GEMM mainloop and attention (r13: 128thr, exp2) unchanged.

constexpr int kE = 768;
constexpr int kB = 2;
constexpr int kS = 2048;
constexpr int kH = 12;
constexpr int kG = 4;
constexpr int kD = 64;
constexpr int kT = 512;                 // S / G
constexpr int kNSE = kB * kS * kE;      // 3,145,728
constexpr int kEE  = kE * kE;           // 589,824
constexpr int kGEE = kG * kE * kE;      // 2,359,296
constexpr int kGSE = kB * kG * kS * kE; // 12,582,912
constexpr int kQTE = kB * kG * kT * kE; // 3,145,728

// ---------------- scratch (device globals; no allocations allowed) ----------
__device__ __nv_bfloat16 c_q_h[kNSE], c_q_l[kNSE];
__device__ __nv_bfloat16 c_k_h[kNSE], c_k_l[kNSE];
__device__ __nv_bfloat16 c_v_h[kNSE], c_v_l[kNSE];
__device__ __nv_bfloat16 a_q_h[kNSE], a_q_l[kNSE];
__device__ __nv_bfloat16 a_k_h[kNSE], a_k_l[kNSE];
__device__ __nv_bfloat16 a_x_h[kNSE], a_x_l[kNSE];
__device__ __nv_bfloat16 a_qi_h[kQTE], a_qi_l[kQTE];
__device__ __nv_bfloat16 a_ki_h[kGSE], a_ki_l[kGSE];
__device__ __nv_bfloat16 a_vi_h[kGSE], a_vi_l[kGSE];
__device__ __nv_bfloat16 a_c_h[kQTE], a_c_l[kQTE];
__device__ __nv_bfloat16 w0_h[kEE],  w0_l[kEE];
__device__ __nv_bfloat16 w1_h[kEE],  w1_l[kEE];
__device__ __nv_bfloat16 w2_h[kEE],  w2_l[kEE];
__device__ __nv_bfloat16 wq_h[kGEE], wq_l[kGEE];
__device__ __nv_bfloat16 wk_h[kGEE], wk_l[kGEE];
__device__ __nv_bfloat16 wv_h[kGEE], wv_l[kGEE];
__device__ __nv_bfloat16 wo_h[kGEE], wo_l[kGEE];

// ---------------- helpers ----------------------------------------------------
__device__ __forceinline__ uint32_t smem_u32(const void* p) {
    uint32_t a;
    asm("{ .reg .u64 t; cvta.to.shared.u64 t, %1; cvt.u32.u64 %0, t; }"
        : "=r"(a) : "l"(p));
    return a;
}
__device__ __forceinline__ void cp16(uint32_t dst, const void* src) {
    asm volatile("cp.async.cg.shared.global [%0], [%1], 16;" :: "r"(dst), "l"(src));
}
#define CP_COMMIT() asm volatile("cp.async.commit_group;" ::: "memory")
#define CP_WAIT0()  asm volatile("cp.async.wait_group 0;" ::: "memory")

__device__ __forceinline__ void mma_bf16(float* c, const uint32_t* a, const uint32_t* b) {
    asm volatile(
        "mma.sync.aligned.m16n8k16.row.col.f32.bf16.bf16.f32 "
        "{%0,%1,%2,%3}, {%4,%5,%6,%7}, {%8,%9}, {%0,%1,%2,%3};"
        : "+f"(c[0]), "+f"(c[1]), "+f"(c[2]), "+f"(c[3])
        : "r"(a[0]), "r"(a[1]), "r"(a[2]), "r"(a[3]), "r"(b[0]), "r"(b[1]));
}
__device__ __forceinline__ void ldsm4(uint32_t& r0, uint32_t& r1, uint32_t& r2,
                                      uint32_t& r3, uint32_t addr) {
    asm volatile("ldmatrix.sync.aligned.m8n8.x4.shared.b16 {%0,%1,%2,%3}, [%4];"
                 : "=r"(r0), "=r"(r1), "=r"(r2), "=r"(r3) : "r"(addr));
}
__device__ __forceinline__ void ldsm4t(uint32_t& r0, uint32_t& r1, uint32_t& r2,
                                       uint32_t& r3, uint32_t addr) {
    asm volatile("ldmatrix.sync.aligned.m8n8.x4.trans.shared.b16 {%0,%1,%2,%3}, [%4];"
                 : "=r"(r0), "=r"(r1), "=r"(r2), "=r"(r3) : "r"(addr));
}

__device__ __forceinline__ void split1(float x, __nv_bfloat16& h, __nv_bfloat16& l) {
    h = __float2bfloat16(x);
    l = __float2bfloat16(x - __bfloat162float(h));
}
__device__ __forceinline__ uint32_t pk(__nv_bfloat16 a, __nv_bfloat16 b) {
    uint16_t ua = *(uint16_t*)&a, ub = *(uint16_t*)&b;
    return (uint32_t)ua | ((uint32_t)ub << 16);
}

// ---------------- row mappings (runtime mode) --------------------------------
__device__ __forceinline__ int in_row_rt(int mode, int m) {
    if (mode == 1) {
        int b = m >> 11; int g = (m >> 9) & 3; int t = m & 511;
        return (b << 11) + (t << 2) + g;
    }
    if (mode == 2) {
        int b = m >> 13; int s = m & 2047;
        return (b << 11) + s;
    }
    return m;
}
__device__ __forceinline__ int perm_row(int m) {
    int b = m >> 11; int g = (m >> 9) & 3; int t = m & 511;
    return (b << 11) + (t << 2) + g;
}

// ---------------- hi/lo conversion kernels -----------------------------------
__device__ __forceinline__ void cvt_one(const float4* in, uint2* h, uint2* l, int i) {
    float4 v = in[i];
    __nv_bfloat16 h0, l0, h1, l1, h2, l2, h3, l3;
    split1(v.x, h0, l0); split1(v.y, h1, l1);
    split1(v.z, h2, l2); split1(v.w, h3, l3);
    h[i] = make_uint2(pk(h0, h1), pk(h2, h3));
    l[i] = make_uint2(pk(l0, l1), pk(l2, l3));
}
__global__ void cvt_hl(const float4* __restrict__ in, uint2* __restrict__ h,
                       uint2* __restrict__ l, int n4) {
    int i = blockIdx.x * 256 + threadIdx.x;
    if (i < n4) cvt_one(in, h, l, i);
}
__global__ void cvt_hl3(const float4* __restrict__ i0, uint2* __restrict__ h0, uint2* __restrict__ l0,
                        const float4* __restrict__ i1, uint2* __restrict__ h1, uint2* __restrict__ l1,
                        const float4* __restrict__ i2, uint2* __restrict__ h2, uint2* __restrict__ l2,
                        int n4) {
    int i = blockIdx.x * 256 + threadIdx.x;
    if (i >= n4) return;
    if (blockIdx.y == 0)      cvt_one(i0, h0, l0, i);
    else if (blockIdx.y == 1) cvt_one(i1, h1, l1, i);
    else                      cvt_one(i2, h2, l2, i);
}

// ---------------- bf16x3 HMMA GEMM, job-table merged -------------------------
constexpr int PSTR = 40;               // padded row stride (bf16 elems)
constexpr int MATB = 128 * PSTR * 2;   // 10240 B per matrix
constexpr int BUFB = 4 * MATB;         // 40960 B per buffer (Ah|Al|Wh|Wl)
constexpr int kSmemGemm = 2 * BUFB;    // 81920 B

struct Job {
    const __nv_bfloat16 *Ah, *Al, *Wh, *Wl;
    const float* bias;
    __nv_bfloat16 *outH, *outL;
    float* outF;            // non-null -> fp32 output (ignores outH/outL)
    float scale;
    int mode;               // 0 plain / 1 q-gather / 2 kv-broadcast / 3 out-perm
    int mblocks;            // number of 128-row m blocks
};
struct Jobs3 { Job j[3]; };

__global__ __launch_bounds__(256, 2)
void gemm_any(Jobs3 jobs) {
    extern __shared__ char s_raw[];
    const uint32_t sb = smem_u32(s_raw);

    const int tid = threadIdx.x;
    int by = blockIdx.y;
    int ji = 0, jbase = 0;
    if (by >= jobs.j[0].mblocks) {
        jbase = jobs.j[0].mblocks; ji = 1;
        if (by >= jbase + jobs.j[1].mblocks) { jbase += jobs.j[1].mblocks; ji = 2; }
    }
    const Job J = jobs.j[ji];
    const int mode = J.mode;
    const int m0 = (by - jbase) * 128;
    const int n0 = blockIdx.x * 128;

    int g = 0;
    if (mode == 1 || mode == 3) g = (m0 >> 9) & 3;
    if (mode == 2)              g = (m0 >> 11) & 3;
    const __nv_bfloat16* WgH = J.Wh + (size_t)g * kEE;
    const __nv_bfloat16* WgL = J.Wl + (size_t)g * kEE;
    const float* bg = J.bias + (size_t)g * kE;

    const int lrow = tid >> 1;
    const int lhalf = tid & 1;
    const int arow = in_row_rt(mode, m0 + lrow);
    const __nv_bfloat16* pAh = J.Ah + (size_t)arow * kE + lhalf * 16;
    const __nv_bfloat16* pAl = J.Al + (size_t)arow * kE + lhalf * 16;
    const __nv_bfloat16* pWh = WgH + (size_t)(n0 + lrow) * kE + lhalf * 16;
    const __nv_bfloat16* pWl = WgL + (size_t)(n0 + lrow) * kE + lhalf * 16;
    const uint32_t sdst = sb + (uint32_t)(lrow * PSTR + lhalf * 16) * 2;

    const int lane = tid & 31;
    const int wid = tid >> 5;
    const int r0 = (wid & 3) * 32;
    const int c0 = (wid >> 2) * 64;
    const int lr = lane >> 2;
    const int lq = lane & 3;

    const uint32_t lmo = (uint32_t)((lane & 15) * PSTR + (lane >> 4) * 8) * 2;

    float acc[2][8][4];
#pragma unroll
    for (int i = 0; i < 2; i++)
#pragma unroll
        for (int j = 0; j < 8; j++)
#pragma unroll
            for (int q = 0; q < 4; q++) acc[i][j][q] = 0.f;

    {
        cp16(sdst,            pAh); cp16(sdst + 16,            pAh + 8);
        cp16(sdst + MATB,     pAl); cp16(sdst + MATB + 16,     pAl + 8);
        cp16(sdst + 2 * MATB, pWh); cp16(sdst + 2 * MATB + 16, pWh + 8);
        cp16(sdst + 3 * MATB, pWl); cp16(sdst + 3 * MATB + 16, pWl + 8);
        CP_COMMIT();
    }

#pragma unroll 1
    for (int p = 0; p < 24; ++p) {
        CP_WAIT0();
        __syncthreads();
        if (p + 1 < 24) {
            const int go = (p + 1) * 32;
            const uint32_t d = sdst + ((p + 1) & 1) * BUFB;
            cp16(d,            pAh + go); cp16(d + 16,            pAh + go + 8);
            cp16(d + MATB,     pAl + go); cp16(d + MATB + 16,     pAl + go + 8);
            cp16(d + 2 * MATB, pWh + go); cp16(d + 2 * MATB + 16, pWh + go + 8);
            cp16(d + 3 * MATB, pWl + go); cp16(d + 3 * MATB + 16, pWl + go + 8);
            CP_COMMIT();
        }

        const uint32_t bbase = sb + (p & 1) * BUFB;
#pragma unroll
        for (int ks = 0; ks < 2; ++ks) {
            const uint32_t ko = lmo + (uint32_t)(ks * 16) * 2;
            uint32_t AhF[2][4], AlF[2][4], BF[8][2];
#pragma unroll
            for (int i = 0; i < 2; i++) {
                const uint32_t ab = bbase + (uint32_t)((r0 + i * 16) * PSTR) * 2 + ko;
                ldsm4(AhF[i][0], AhF[i][1], AhF[i][2], AhF[i][3], ab);
                ldsm4(AlF[i][0], AlF[i][1], AlF[i][2], AlF[i][3], ab + MATB);
            }
#pragma unroll
            for (int u = 0; u < 4; u++) {
                uint32_t q0, q1, q2, q3;
                ldsm4(q0, q1, q2, q3,
                      bbase + 2 * MATB + (uint32_t)((c0 + u * 16) * PSTR) * 2 + ko);
                BF[2 * u][0] = q0; BF[2 * u][1] = q2;
                BF[2 * u + 1][0] = q1; BF[2 * u + 1][1] = q3;
            }
#pragma unroll
            for (int j = 0; j < 8; j++) {
                mma_bf16(acc[0][j], AhF[0], BF[j]);
                mma_bf16(acc[1][j], AhF[1], BF[j]);
            }
#pragma unroll
            for (int j = 0; j < 8; j++) {
                mma_bf16(acc[0][j], AlF[0], BF[j]);
                mma_bf16(acc[1][j], AlF[1], BF[j]);
            }
#pragma unroll
            for (int u = 0; u < 4; u++) {
                uint32_t q0, q1, q2, q3;
                ldsm4(q0, q1, q2, q3,
                      bbase + 3 * MATB + (uint32_t)((c0 + u * 16) * PSTR) * 2 + ko);
                BF[2 * u][0] = q0; BF[2 * u][1] = q2;
                BF[2 * u + 1][0] = q1; BF[2 * u + 1][1] = q3;
            }
#pragma unroll
            for (int j = 0; j < 8; j++) {
                mma_bf16(acc[0][j], AhF[0], BF[j]);
                mma_bf16(acc[1][j], AhF[1], BF[j]);
            }
        }
    }

    // epilogue
#pragma unroll
    for (int i = 0; i < 2; i++) {
#pragma unroll
        for (int half = 0; half < 2; half++) {
            const int m = m0 + r0 + i * 16 + lr + half * 8;
            const size_t orow = (mode == 3) ? (size_t)perm_row(m) : (size_t)m;
#pragma unroll
            for (int j = 0; j < 8; j++) {
                const int col = n0 + c0 + j * 8 + lq * 2;
                const float2 bb = *(const float2*)(bg + col);
                float x0 = acc[i][j][half * 2 + 0] + bb.x;
                float x1 = acc[i][j][half * 2 + 1] + bb.y;
                if (J.outF) {
                    *(float2*)(J.outF + orow * kE + col) = make_float2(x0, x1);
                } else {
                    x0 *= J.scale; x1 *= J.scale;
                    __nv_bfloat16 h0, l0, h1, l1;
                    split1(x0, h0, l0); split1(x1, h1, l1);
                    *(uint32_t*)(J.outH + orow * kE + col) = pk(h0, h1);
                    *(uint32_t*)(J.outL + orow * kE + col) = pk(l0, l1);
                }
            }
        }
    }
}

// ---------------- HMMA flash attention (r13: 128 threads, exp2) --------------
constexpr int ASTR = 72;   // smem row stride in bf16 elems

__global__ __launch_bounds__(128, 2)
void attn_mma() {
    __shared__ __align__(16) uint16_t sKh[64 * ASTR], sKl[64 * ASTR];
    __shared__ __align__(16) uint16_t sVh[64 * ASTR], sVl[64 * ASTR];

    const int tid = threadIdx.x;
    const int wid = tid >> 5;
    const int lane = tid & 31;
    const int lr = lane >> 2;
    const int lq = lane & 3;

    const int y = blockIdx.y;
    const int b = y / (kG * kH);
    const int g = (y / kH) & 3;
    const int h = y % kH;
    const int q0 = blockIdx.x * 64;

    const size_t head_q  = ((size_t)(b * kG + g) * kT) * kE + h * kD;
    const size_t head_kv = ((size_t)(b * kG + g) * kS) * kE + h * kD;

    // Q fragments; q pre-scaled by 0.125*log2(e) upstream (base-2 softmax).
    uint32_t qh[4][4], ql[4][4];
    {
        const size_t r0o = head_q + (size_t)(q0 + wid * 16 + lr) * kE;
        const size_t r1o = r0o + 8 * kE;
#pragma unroll
        for (int kc = 0; kc < 4; kc++) {
            const int cA = kc * 16 + lq * 2;
            qh[kc][0] = *(const uint32_t*)(a_qi_h + r0o + cA);
            qh[kc][1] = *(const uint32_t*)(a_qi_h + r1o + cA);
            qh[kc][2] = *(const uint32_t*)(a_qi_h + r0o + cA + 8);
            qh[kc][3] = *(const uint32_t*)(a_qi_h + r1o + cA + 8);
            ql[kc][0] = *(const uint32_t*)(a_qi_l + r0o + cA);
            ql[kc][1] = *(const uint32_t*)(a_qi_l + r1o + cA);
            ql[kc][2] = *(const uint32_t*)(a_qi_l + r0o + cA + 8);
            ql[kc][3] = *(const uint32_t*)(a_qi_l + r1o + cA + 8);
        }
    }

    const uint32_t lko = (uint32_t)((((lane >> 3) & 1) * 8 + (lane & 7)) * ASTR * 2
                                    + (lane >> 4) * 16);
    const uint32_t bKh = smem_u32(sKh), bKl = smem_u32(sKl);
    const uint32_t bVh = smem_u32(sVh), bVl = smem_u32(sVl);

    float o[8][4];
#pragma unroll
    for (int j = 0; j < 8; j++)
#pragma unroll
        for (int e = 0; e < 4; e++) o[j][e] = 0.f;
    float m0 = -1e30f, m1 = -1e30f, l0 = 0.f, l1 = 0.f;

    const int trow = tid >> 1;
    const int tcol = (tid & 1) * 32;
    const uint32_t sof = (uint32_t)(trow * ASTR + tcol) * 2;

#pragma unroll 1
    for (int kv = 0; kv < kS; kv += 64) {
        {
            const size_t gofs = head_kv + (size_t)(kv + trow) * kE + tcol;
#pragma unroll
            for (int c = 0; c < 4; c++) {
                *(uint4*)((char*)sKh + sof + c * 16) = *(const uint4*)(a_ki_h + gofs + c * 8);
                *(uint4*)((char*)sKl + sof + c * 16) = *(const uint4*)(a_ki_l + gofs + c * 8);
                *(uint4*)((char*)sVh + sof + c * 16) = *(const uint4*)(a_vi_h + gofs + c * 8);
                *(uint4*)((char*)sVl + sof + c * 16) = *(const uint4*)(a_vi_l + gofs + c * 8);
            }
        }
        __syncthreads();

        // ---- QK ----
        float acc[8][4];
#pragma unroll
        for (int j = 0; j < 8; j++)
#pragma unroll
            for (int e = 0; e < 4; e++) acc[j][e] = 0.f;

#pragma unroll
        for (int kc = 0; kc < 4; kc++) {
            uint32_t kb[8][2];
#pragma unroll
            for (int u = 0; u < 4; u++) {
                uint32_t r0, r1, r2, r3;
                ldsm4(r0, r1, r2, r3, bKh + (uint32_t)(u * 16 * ASTR + kc * 16) * 2 + lko);
                kb[2 * u][0] = r0; kb[2 * u][1] = r2;
                kb[2 * u + 1][0] = r1; kb[2 * u + 1][1] = r3;
            }
#pragma unroll
            for (int j = 0; j < 8; j++) mma_bf16(acc[j], qh[kc], kb[j]);
#pragma unroll
            for (int j = 0; j < 8; j++) mma_bf16(acc[j], ql[kc], kb[j]);
#pragma unroll
            for (int u = 0; u < 4; u++) {
                uint32_t r0, r1, r2, r3;
                ldsm4(r0, r1, r2, r3, bKl + (uint32_t)(u * 16 * ASTR + kc * 16) * 2 + lko);
                kb[2 * u][0] = r0; kb[2 * u][1] = r2;
                kb[2 * u + 1][0] = r1; kb[2 * u + 1][1] = r3;
            }
#pragma unroll
            for (int j = 0; j < 8; j++) mma_bf16(acc[j], qh[kc], kb[j]);
        }

        // ---- online softmax (base-2) ----
        float mt0 = -1e30f, mt1 = -1e30f;
#pragma unroll
        for (int j = 0; j < 8; j++) {
            mt0 = fmaxf(mt0, fmaxf(acc[j][0], acc[j][1]));
            mt1 = fmaxf(mt1, fmaxf(acc[j][2], acc[j][3]));
        }
        mt0 = fmaxf(mt0, __shfl_xor_sync(0xffffffffu, mt0, 1));
        mt0 = fmaxf(mt0, __shfl_xor_sync(0xffffffffu, mt0, 2));
        mt1 = fmaxf(mt1, __shfl_xor_sync(0xffffffffu, mt1, 1));
        mt1 = fmaxf(mt1, __shfl_xor_sync(0xffffffffu, mt1, 2));
        const float mn0 = fmaxf(m0, mt0);
        const float mn1 = fmaxf(m1, mt1);
        const float cr0 = exp2f(m0 - mn0);
        const float cr1 = exp2f(m1 - mn1);
        m0 = mn0; m1 = mn1;
        l0 *= cr0; l1 *= cr1;
#pragma unroll
        for (int j = 0; j < 8; j++) {
            o[j][0] *= cr0; o[j][1] *= cr0;
            o[j][2] *= cr1; o[j][3] *= cr1;
        }

        uint32_t pha[4][4], pla[4][4];
#pragma unroll
        for (int j = 0; j < 8; j++) {
            const float p0 = exp2f(acc[j][0] - m0);
            const float p1 = exp2f(acc[j][1] - m0);
            const float p2 = exp2f(acc[j][2] - m1);
            const float p3 = exp2f(acc[j][3] - m1);
            l0 += p0 + p1; l1 += p2 + p3;
            __nv_bfloat16 h0, e0, h1, e1, h2, e2, h3, e3;
            split1(p0, h0, e0); split1(p1, h1, e1);
            split1(p2, h2, e2); split1(p3, h3, e3);
            const int sc = j >> 1, hh = (j & 1) * 2;
            pha[sc][hh + 0] = pk(h0, h1); pha[sc][hh + 1] = pk(h2, h3);
            pla[sc][hh + 0] = pk(e0, e1); pla[sc][hh + 1] = pk(e2, e3);
        }

        // ---- PV ----
#pragma unroll
        for (int sc = 0; sc < 4; sc++) {
            uint32_t vb[8][2];
#pragma unroll
            for (int u = 0; u < 4; u++) {
                uint32_t r0, r1, r2, r3;
                ldsm4t(r0, r1, r2, r3, bVh + (uint32_t)(sc * 16 * ASTR + u * 16) * 2 + lko);
                vb[2 * u][0] = r0; vb[2 * u][1] = r1;
                vb[2 * u + 1][0] = r2; vb[2 * u + 1][1] = r3;
            }
#pragma unroll
            for (int j = 0; j < 8; j++) mma_bf16(o[j], pha[sc], vb[j]);
#pragma unroll
            for (int j = 0; j < 8; j++) mma_bf16(o[j], pla[sc], vb[j]);
#pragma unroll
            for (int u = 0; u < 4; u++) {
                uint32_t r0, r1, r2, r3;
                ldsm4t(r0, r1, r2, r3, bVl + (uint32_t)(sc * 16 * ASTR + u * 16) * 2 + lko);
                vb[2 * u][0] = r0; vb[2 * u][1] = r1;
                vb[2 * u + 1][0] = r2; vb[2 * u + 1][1] = r3;
            }
#pragma unroll
            for (int j = 0; j < 8; j++) mma_bf16(o[j], pha[sc], vb[j]);
        }
        __syncthreads();
    }

    // ---- epilogue ----
    l0 += __shfl_xor_sync(0xffffffffu, l0, 1);
    l0 += __shfl_xor_sync(0xffffffffu, l0, 2);
    l1 += __shfl_xor_sync(0xffffffffu, l1, 1);
    l1 += __shfl_xor_sync(0xffffffffu, l1, 2);
    const float inv0 = 1.0f / l0, inv1 = 1.0f / l1;
    const size_t r0o = head_q + (size_t)(q0 + wid * 16 + lr) * kE;
    const size_t r1o = r0o + 8 * kE;
#pragma unroll
    for (int j = 0; j < 8; j++) {
        const int col = j * 8 + lq * 2;
        __nv_bfloat16 h0, e0, h1, e1;
        split1(o[j][0] * inv0, h0, e0); split1(o[j][1] * inv0, h1, e1);
        *(uint32_t*)(a_c_h + r0o + col) = pk(h0, h1);
        *(uint32_t*)(a_c_l + r0o + col) = pk(e0, e1);
        split1(o[j][2] * inv1, h0, e0); split1(o[j][3] * inv1, h1, e1);
        *(uint32_t*)(a_c_h + r1o + col) = pk(h0, h1);
        *(uint32_t*)(a_c_l + r1o + col) = pk(e0, e1);
    }
}

// ---------------- launch ----------------------------------------------------
extern "C" void kernel_launch(void* const* d_in, const int* in_sizes, int n_in,
                              void* d_out, int out_size) {
    const float* query = (const float*)d_in[0];
    const float* key   = (const float*)d_in[1];
    const float* value = (const float*)d_in[2];
    const float* Wqg   = (const float*)d_in[3];
    const float* bqg   = (const float*)d_in[4];
    const float* Wk    = (const float*)d_in[5];
    const float* bk    = (const float*)d_in[6];
    const float* Wv    = (const float*)d_in[7];
    const float* bv    = (const float*)d_in[8];
    const float* Wq_in = (const float*)d_in[9];
    const float* bq_in = (const float*)d_in[10];
    const float* Wk_in = (const float*)d_in[11];
    const float* bk_in = (const float*)d_in[12];
    const float* Wv_in = (const float*)d_in[13];
    const float* bv_in = (const float*)d_in[14];
    const float* Wout  = (const float*)d_in[15];
    const float* bout  = (const float*)d_in[16];

#define SYM(p, s) void* p; cudaGetSymbolAddress(&p, s)
    SYM(p_cq_h, c_q_h); SYM(p_cq_l, c_q_l);
    SYM(p_ck_h, c_k_h); SYM(p_ck_l, c_k_l);
    SYM(p_cv_h, c_v_h); SYM(p_cv_l, c_v_l);
    SYM(p_aq_h, a_q_h); SYM(p_aq_l, a_q_l);
    SYM(p_ak_h, a_k_h); SYM(p_ak_l, a_k_l);
    SYM(p_ax_h, a_x_h); SYM(p_ax_l, a_x_l);
    SYM(p_qi_h, a_qi_h); SYM(p_qi_l, a_qi_l);
    SYM(p_ki_h, a_ki_h); SYM(p_ki_l, a_ki_l);
    SYM(p_vi_h, a_vi_h); SYM(p_vi_l, a_vi_l);
    SYM(p_ac_h, a_c_h); SYM(p_ac_l, a_c_l);
    SYM(p_w0_h, w0_h);  SYM(p_w0_l, w0_l);
    SYM(p_w1_h, w1_h);  SYM(p_w1_l, w1_l);
    SYM(p_w2_h, w2_h);  SYM(p_w2_l, w2_l);
    SYM(p_wq_h, wq_h);  SYM(p_wq_l, wq_l);
    SYM(p_wk_h, wk_h);  SYM(p_wk_l, wk_l);
    SYM(p_wv_h, wv_h);  SYM(p_wv_l, wv_l);
    SYM(p_wo_h, wo_h);  SYM(p_wo_l, wo_l);
#undef SYM

    cudaFuncSetAttribute(gemm_any, cudaFuncAttributeMaxDynamicSharedMemorySize, kSmemGemm);

    typedef const __nv_bfloat16* BP;
    typedef __nv_bfloat16* BPm;
    typedef const float4* F4;
    typedef uint2* U2;

    // hi/lo conversions
    cvt_hl3<<<dim3(kNSE / 4 / 256, 3), 256>>>(
        (F4)query, (U2)p_cq_h, (U2)p_cq_l,
        (F4)key,   (U2)p_ck_h, (U2)p_ck_l,
        (F4)value, (U2)p_cv_h, (U2)p_cv_l, kNSE / 4);
    cvt_hl3<<<dim3(kEE / 4 / 256, 3), 256>>>(
        (F4)Wqg, (U2)p_w0_h, (U2)p_w0_l,
        (F4)Wk,  (U2)p_w1_h, (U2)p_w1_l,
        (F4)Wv,  (U2)p_w2_h, (U2)p_w2_l, kEE / 4);
    cvt_hl3<<<dim3(kGEE / 4 / 256, 3), 256>>>(
        (F4)Wq_in, (U2)p_wq_h, (U2)p_wq_l,
        (F4)Wk_in, (U2)p_wk_h, (U2)p_wk_l,
        (F4)Wv_in, (U2)p_wv_h, (U2)p_wv_l, kGEE / 4);
    cvt_hl<<<kGEE / 4 / 256, 256>>>((F4)Wout, (U2)p_wo_h, (U2)p_wo_l, kGEE / 4);

    const float kQScale = 0.125f * 1.44269504f;   // 1/sqrt(D) * log2(e)
    auto mkjob = [](const void* Ah, const void* Al, const void* Wh, const void* Wl,
                    const float* bias, void* outH, void* outL, float* outF,
                    float scale, int mode, int mblocks) {
        Job j;
        j.Ah = (BP)Ah; j.Al = (BP)Al; j.Wh = (BP)Wh; j.Wl = (BP)Wl;
        j.bias = bias; j.outH = (BPm)outH; j.outL = (BPm)outL; j.outF = outF;
        j.scale = scale; j.mode = mode; j.mblocks = mblocks;
        return j;
    };

    // launch 1: outer projections q|k|v  (3 x 32 mblocks = grid.y 96)
    Jobs3 outer;
    outer.j[0] = mkjob(p_cq_h, p_cq_l, p_w0_h, p_w0_l, bqg, p_aq_h, p_aq_l,
                       nullptr, 1.0f, 0, 32);
    outer.j[1] = mkjob(p_ck_h, p_ck_l, p_w1_h, p_w1_l, bk, p_ak_h, p_ak_l,
                       nullptr, 1.0f, 0, 32);
    outer.j[2] = mkjob(p_cv_h, p_cv_l, p_w2_h, p_w2_l, bv, p_ax_h, p_ax_l,
                       nullptr, 1.0f, 0, 32);
    gemm_any<<<dim3(6, 96), 256, kSmemGemm>>>(outer);

    // launch 2: in-projections qi|ki|vi  (32 + 128 + 128 = grid.y 288)
    Jobs3 inproj;
    inproj.j[0] = mkjob(p_aq_h, p_aq_l, p_wq_h, p_wq_l, bq_in, p_qi_h, p_qi_l,
                        nullptr, kQScale, 1, 32);
    inproj.j[1] = mkjob(p_ak_h, p_ak_l, p_wk_h, p_wk_l, bk_in, p_ki_h, p_ki_l,
                        nullptr, 1.0f, 2, 128);
    inproj.j[2] = mkjob(p_ax_h, p_ax_l, p_wv_h, p_wv_l, bv_in, p_vi_h, p_vi_l,
                        nullptr, 1.0f, 2, 128);
    gemm_any<<<dim3(6, 288), 256, kSmemGemm>>>(inproj);

    // launch 3: attention
    attn_mma<<<dim3(kT / 64, kB * kG * kH), dim3(128)>>>();

    // launch 4: out-projection (permuted scatter to d_out)
    Jobs3 outp;
    outp.j[0] = mkjob(p_ac_h, p_ac_l, p_wo_h, p_wo_l, bout, nullptr, nullptr,
                      (float*)d_out, 1.0f, 3, 32);
    outp.j[1] = outp.j[0]; outp.j[1].mblocks = 0;
    outp.j[2] = outp.j[0]; outp.j[2].mblocks = 0;
    gemm_any<<<dim3(6, 32), 256, kSmemGemm>>>(outp);
}

// round 15
// speedup vs baseline: 1.3953x; 1.1772x over previous
#include <cuda_runtime.h>
#include <cuda_bf16.h>
#include <cuda_fp16.h>
#include <cstdint>

// GroupQueryAttention: B=2, S=2048, E=768, H=12, G=4, D=64, T=512
// Round 15: precision-tuned attention. GEMM chain stays bf16x3 (r14 merged
// launches). Attention inputs qi/ki/vi emitted as fp16 (Q,K,V single-
// precision; P 2-pass fp16), fixed-offset base-2 softmax (no online max).
// Error budget: score abs err ~6e-5, context rel ~2.4e-4 << 1e-3 gate.

constexpr int kE = 768;
constexpr int kB = 2;
constexpr int kS = 2048;
constexpr int kH = 12;
constexpr int kG = 4;
constexpr int kD = 64;
constexpr int kT = 512;                 // S / G
constexpr int kNSE = kB * kS * kE;      // 3,145,728
constexpr int kEE  = kE * kE;           // 589,824
constexpr int kGEE = kG * kE * kE;      // 2,359,296
constexpr int kGSE = kB * kG * kS * kE; // 12,582,912
constexpr int kQTE = kB * kG * kT * kE; // 3,145,728

// ---------------- scratch (device globals; no allocations allowed) ----------
__device__ __nv_bfloat16 c_q_h[kNSE], c_q_l[kNSE];
__device__ __nv_bfloat16 c_k_h[kNSE], c_k_l[kNSE];
__device__ __nv_bfloat16 c_v_h[kNSE], c_v_l[kNSE];
__device__ __nv_bfloat16 a_q_h[kNSE], a_q_l[kNSE];
__device__ __nv_bfloat16 a_k_h[kNSE], a_k_l[kNSE];
__device__ __nv_bfloat16 a_x_h[kNSE], a_x_l[kNSE];
__device__ __half        a_qi2[kQTE];               // fp16 q (pre-scaled)
__device__ __half        a_ki2[kGSE];               // fp16 k
__device__ __half        a_vi2[kGSE];               // fp16 v
__device__ __nv_bfloat16 a_c_h[kQTE], a_c_l[kQTE];  // context (bf16 hi/lo)
__device__ __nv_bfloat16 w0_h[kEE],  w0_l[kEE];
__device__ __nv_bfloat16 w1_h[kEE],  w1_l[kEE];
__device__ __nv_bfloat16 w2_h[kEE],  w2_l[kEE];
__device__ __nv_bfloat16 wq_h[kGEE], wq_l[kGEE];
__device__ __nv_bfloat16 wk_h[kGEE], wk_l[kGEE];
__device__ __nv_bfloat16 wv_h[kGEE], wv_l[kGEE];
__device__ __nv_bfloat16 wo_h[kGEE], wo_l[kGEE];

// ---------------- helpers ----------------------------------------------------
__device__ __forceinline__ uint32_t smem_u32(const void* p) {
    uint32_t a;
    asm("{ .reg .u64 t; cvta.to.shared.u64 t, %1; cvt.u32.u64 %0, t; }"
        : "=r"(a) : "l"(p));
    return a;
}
__device__ __forceinline__ void cp16(uint32_t dst, const void* src) {
    asm volatile("cp.async.cg.shared.global [%0], [%1], 16;" :: "r"(dst), "l"(src));
}
#define CP_COMMIT() asm volatile("cp.async.commit_group;" ::: "memory")
#define CP_WAIT0()  asm volatile("cp.async.wait_group 0;" ::: "memory")

__device__ __forceinline__ void mma_bf16(float* c, const uint32_t* a, const uint32_t* b) {
    asm volatile(
        "mma.sync.aligned.m16n8k16.row.col.f32.bf16.bf16.f32 "
        "{%0,%1,%2,%3}, {%4,%5,%6,%7}, {%8,%9}, {%0,%1,%2,%3};"
        : "+f"(c[0]), "+f"(c[1]), "+f"(c[2]), "+f"(c[3])
        : "r"(a[0]), "r"(a[1]), "r"(a[2]), "r"(a[3]), "r"(b[0]), "r"(b[1]));
}
__device__ __forceinline__ void mma_f16(float* c, const uint32_t* a, const uint32_t* b) {
    asm volatile(
        "mma.sync.aligned.m16n8k16.row.col.f32.f16.f16.f32 "
        "{%0,%1,%2,%3}, {%4,%5,%6,%7}, {%8,%9}, {%0,%1,%2,%3};"
        : "+f"(c[0]), "+f"(c[1]), "+f"(c[2]), "+f"(c[3])
        : "r"(a[0]), "r"(a[1]), "r"(a[2]), "r"(a[3]), "r"(b[0]), "r"(b[1]));
}
__device__ __forceinline__ void ldsm4(uint32_t& r0, uint32_t& r1, uint32_t& r2,
                                      uint32_t& r3, uint32_t addr) {
    asm volatile("ldmatrix.sync.aligned.m8n8.x4.shared.b16 {%0,%1,%2,%3}, [%4];"
                 : "=r"(r0), "=r"(r1), "=r"(r2), "=r"(r3) : "r"(addr));
}
__device__ __forceinline__ void ldsm4t(uint32_t& r0, uint32_t& r1, uint32_t& r2,
                                       uint32_t& r3, uint32_t addr) {
    asm volatile("ldmatrix.sync.aligned.m8n8.x4.trans.shared.b16 {%0,%1,%2,%3}, [%4];"
                 : "=r"(r0), "=r"(r1), "=r"(r2), "=r"(r3) : "r"(addr));
}

__device__ __forceinline__ void split1(float x, __nv_bfloat16& h, __nv_bfloat16& l) {
    h = __float2bfloat16(x);
    l = __float2bfloat16(x - __bfloat162float(h));
}
__device__ __forceinline__ uint32_t pk(__nv_bfloat16 a, __nv_bfloat16 b) {
    uint16_t ua = *(uint16_t*)&a, ub = *(uint16_t*)&b;
    return (uint32_t)ua | ((uint32_t)ub << 16);
}
__device__ __forceinline__ uint32_t pkh(__half a, __half b) {
    uint16_t ua = *(uint16_t*)&a, ub = *(uint16_t*)&b;
    return (uint32_t)ua | ((uint32_t)ub << 16);
}
__device__ __forceinline__ void splith(float x, __half& h, __half& l) {
    h = __float2half_rn(x);
    l = __float2half_rn(x - __half2float(h));
}

// ---------------- row mappings (runtime mode) --------------------------------
__device__ __forceinline__ int in_row_rt(int mode, int m) {
    if (mode == 1) {
        int b = m >> 11; int g = (m >> 9) & 3; int t = m & 511;
        return (b << 11) + (t << 2) + g;
    }
    if (mode == 2) {
        int b = m >> 13; int s = m & 2047;
        return (b << 11) + s;
    }
    return m;
}
__device__ __forceinline__ int perm_row(int m) {
    int b = m >> 11; int g = (m >> 9) & 3; int t = m & 511;
    return (b << 11) + (t << 2) + g;
}

// ---------------- hi/lo conversion kernels -----------------------------------
__device__ __forceinline__ void cvt_one(const float4* in, uint2* h, uint2* l, int i) {
    float4 v = in[i];
    __nv_bfloat16 h0, l0, h1, l1, h2, l2, h3, l3;
    split1(v.x, h0, l0); split1(v.y, h1, l1);
    split1(v.z, h2, l2); split1(v.w, h3, l3);
    h[i] = make_uint2(pk(h0, h1), pk(h2, h3));
    l[i] = make_uint2(pk(l0, l1), pk(l2, l3));
}
__global__ void cvt_hl(const float4* __restrict__ in, uint2* __restrict__ h,
                       uint2* __restrict__ l, int n4) {
    int i = blockIdx.x * 256 + threadIdx.x;
    if (i < n4) cvt_one(in, h, l, i);
}
__global__ void cvt_hl3(const float4* __restrict__ i0, uint2* __restrict__ h0, uint2* __restrict__ l0,
                        const float4* __restrict__ i1, uint2* __restrict__ h1, uint2* __restrict__ l1,
                        const float4* __restrict__ i2, uint2* __restrict__ h2, uint2* __restrict__ l2,
                        int n4) {
    int i = blockIdx.x * 256 + threadIdx.x;
    if (i >= n4) return;
    if (blockIdx.y == 0)      cvt_one(i0, h0, l0, i);
    else if (blockIdx.y == 1) cvt_one(i1, h1, l1, i);
    else                      cvt_one(i2, h2, l2, i);
}

// ---------------- bf16x3 HMMA GEMM, job-table merged -------------------------
constexpr int PSTR = 40;               // padded row stride (bf16 elems)
constexpr int MATB = 128 * PSTR * 2;   // 10240 B per matrix
constexpr int BUFB = 4 * MATB;         // 40960 B per buffer (Ah|Al|Wh|Wl)
constexpr int kSmemGemm = 2 * BUFB;    // 81920 B

struct Job {
    const __nv_bfloat16 *Ah, *Al, *Wh, *Wl;
    const float* bias;
    void *o0, *o1;          // otype 0: o0=float*; 1: bf16 h,l; 2: half* h
    float scale;
    int mode;               // 0 plain / 1 q-gather / 2 kv-broadcast / 3 out-perm
    int otype;              // 0 fp32 / 1 bf16 hi+lo / 2 fp16 single
    int mblocks;
};
struct Jobs3 { Job j[3]; };

__global__ __launch_bounds__(256, 2)
void gemm_any(Jobs3 jobs) {
    extern __shared__ char s_raw[];
    const uint32_t sb = smem_u32(s_raw);

    const int tid = threadIdx.x;
    int by = blockIdx.y;
    int ji = 0, jbase = 0;
    if (by >= jobs.j[0].mblocks) {
        jbase = jobs.j[0].mblocks; ji = 1;
        if (by >= jbase + jobs.j[1].mblocks) { jbase += jobs.j[1].mblocks; ji = 2; }
    }
    const Job J = jobs.j[ji];
    const int mode = J.mode;
    const int m0 = (by - jbase) * 128;
    const int n0 = blockIdx.x * 128;

    int g = 0;
    if (mode == 1 || mode == 3) g = (m0 >> 9) & 3;
    if (mode == 2)              g = (m0 >> 11) & 3;
    const __nv_bfloat16* WgH = J.Wh + (size_t)g * kEE;
    const __nv_bfloat16* WgL = J.Wl + (size_t)g * kEE;
    const float* bg = J.bias + (size_t)g * kE;

    const int lrow = tid >> 1;
    const int lhalf = tid & 1;
    const int arow = in_row_rt(mode, m0 + lrow);
    const __nv_bfloat16* pAh = J.Ah + (size_t)arow * kE + lhalf * 16;
    const __nv_bfloat16* pAl = J.Al + (size_t)arow * kE + lhalf * 16;
    const __nv_bfloat16* pWh = WgH + (size_t)(n0 + lrow) * kE + lhalf * 16;
    const __nv_bfloat16* pWl = WgL + (size_t)(n0 + lrow) * kE + lhalf * 16;
    const uint32_t sdst = sb + (uint32_t)(lrow * PSTR + lhalf * 16) * 2;

    const int lane = tid & 31;
    const int wid = tid >> 5;
    const int r0 = (wid & 3) * 32;
    const int c0 = (wid >> 2) * 64;
    const int lr = lane >> 2;
    const int lq = lane & 3;

    const uint32_t lmo = (uint32_t)((lane & 15) * PSTR + (lane >> 4) * 8) * 2;

    float acc[2][8][4];
#pragma unroll
    for (int i = 0; i < 2; i++)
#pragma unroll
        for (int j = 0; j < 8; j++)
#pragma unroll
            for (int q = 0; q < 4; q++) acc[i][j][q] = 0.f;

    {
        cp16(sdst,            pAh); cp16(sdst + 16,            pAh + 8);
        cp16(sdst + MATB,     pAl); cp16(sdst + MATB + 16,     pAl + 8);
        cp16(sdst + 2 * MATB, pWh); cp16(sdst + 2 * MATB + 16, pWh + 8);
        cp16(sdst + 3 * MATB, pWl); cp16(sdst + 3 * MATB + 16, pWl + 8);
        CP_COMMIT();
    }

#pragma unroll 1
    for (int p = 0; p < 24; ++p) {
        CP_WAIT0();
        __syncthreads();
        if (p + 1 < 24) {
            const int go = (p + 1) * 32;
            const uint32_t d = sdst + ((p + 1) & 1) * BUFB;
            cp16(d,            pAh + go); cp16(d + 16,            pAh + go + 8);
            cp16(d + MATB,     pAl + go); cp16(d + MATB + 16,     pAl + go + 8);
            cp16(d + 2 * MATB, pWh + go); cp16(d + 2 * MATB + 16, pWh + go + 8);
            cp16(d + 3 * MATB, pWl + go); cp16(d + 3 * MATB + 16, pWl + go + 8);
            CP_COMMIT();
        }

        const uint32_t bbase = sb + (p & 1) * BUFB;
#pragma unroll
        for (int ks = 0; ks < 2; ++ks) {
            const uint32_t ko = lmo + (uint32_t)(ks * 16) * 2;
            uint32_t AhF[2][4], AlF[2][4], BF[8][2];
#pragma unroll
            for (int i = 0; i < 2; i++) {
                const uint32_t ab = bbase + (uint32_t)((r0 + i * 16) * PSTR) * 2 + ko;
                ldsm4(AhF[i][0], AhF[i][1], AhF[i][2], AhF[i][3], ab);
                ldsm4(AlF[i][0], AlF[i][1], AlF[i][2], AlF[i][3], ab + MATB);
            }
#pragma unroll
            for (int u = 0; u < 4; u++) {
                uint32_t q0, q1, q2, q3;
                ldsm4(q0, q1, q2, q3,
                      bbase + 2 * MATB + (uint32_t)((c0 + u * 16) * PSTR) * 2 + ko);
                BF[2 * u][0] = q0; BF[2 * u][1] = q2;
                BF[2 * u + 1][0] = q1; BF[2 * u + 1][1] = q3;
            }
#pragma unroll
            for (int j = 0; j < 8; j++) {
                mma_bf16(acc[0][j], AhF[0], BF[j]);
                mma_bf16(acc[1][j], AhF[1], BF[j]);
            }
#pragma unroll
            for (int j = 0; j < 8; j++) {
                mma_bf16(acc[0][j], AlF[0], BF[j]);
                mma_bf16(acc[1][j], AlF[1], BF[j]);
            }
#pragma unroll
            for (int u = 0; u < 4; u++) {
                uint32_t q0, q1, q2, q3;
                ldsm4(q0, q1, q2, q3,
                      bbase + 3 * MATB + (uint32_t)((c0 + u * 16) * PSTR) * 2 + ko);
                BF[2 * u][0] = q0; BF[2 * u][1] = q2;
                BF[2 * u + 1][0] = q1; BF[2 * u + 1][1] = q3;
            }
#pragma unroll
            for (int j = 0; j < 8; j++) {
                mma_bf16(acc[0][j], AhF[0], BF[j]);
                mma_bf16(acc[1][j], AhF[1], BF[j]);
            }
        }
    }

    // epilogue
#pragma unroll
    for (int i = 0; i < 2; i++) {
#pragma unroll
        for (int half = 0; half < 2; half++) {
            const int m = m0 + r0 + i * 16 + lr + half * 8;
            const size_t orow = (mode == 3) ? (size_t)perm_row(m) : (size_t)m;
#pragma unroll
            for (int j = 0; j < 8; j++) {
                const int col = n0 + c0 + j * 8 + lq * 2;
                const float2 bb = *(const float2*)(bg + col);
                float x0 = acc[i][j][half * 2 + 0] + bb.x;
                float x1 = acc[i][j][half * 2 + 1] + bb.y;
                if (J.otype == 0) {
                    *(float2*)((float*)J.o0 + orow * kE + col) = make_float2(x0, x1);
                } else if (J.otype == 1) {
                    x0 *= J.scale; x1 *= J.scale;
                    __nv_bfloat16 h0, l0, h1, l1;
                    split1(x0, h0, l0); split1(x1, h1, l1);
                    *(uint32_t*)((__nv_bfloat16*)J.o0 + orow * kE + col) = pk(h0, h1);
                    *(uint32_t*)((__nv_bfloat16*)J.o1 + orow * kE + col) = pk(l0, l1);
                } else {
                    x0 *= J.scale; x1 *= J.scale;
                    *(uint32_t*)((__half*)J.o0 + orow * kE + col) =
                        pkh(__float2half_rn(x0), __float2half_rn(x1));
                }
            }
        }
    }
}

// ---------------- fp16 HMMA flash attention ----------------------------------
// grid (T/64, B*G*H), 128 threads (4 warps), 3 CTAs/SM. Warp w: 16 q rows.
// BKV=64. Q,K,V single fp16; P 2-pass fp16. Fixed-offset base-2 softmax
// (scores pre-scaled by log2e/8 upstream; constant offset cancels in norm).
constexpr int ASTR = 72;   // smem row stride in fp16 elems

__global__ __launch_bounds__(128, 3)
void attn_mma() {
    __shared__ __align__(16) __half sK[64 * ASTR];
    __shared__ __align__(16) __half sV[64 * ASTR];

    const int tid = threadIdx.x;
    const int wid = tid >> 5;
    const int lane = tid & 31;
    const int lr = lane >> 2;
    const int lq = lane & 3;

    const int y = blockIdx.y;
    const int b = y / (kG * kH);
    const int g = (y / kH) & 3;
    const int h = y % kH;
    const int q0 = blockIdx.x * 64;

    const size_t head_q  = ((size_t)(b * kG + g) * kT) * kE + h * kD;
    const size_t head_kv = ((size_t)(b * kG + g) * kS) * kE + h * kD;

    // Q fragments (fp16 single)
    uint32_t qh[4][4];
    {
        const size_t r0o = head_q + (size_t)(q0 + wid * 16 + lr) * kE;
        const size_t r1o = r0o + 8 * kE;
#pragma unroll
        for (int kc = 0; kc < 4; kc++) {
            const int cA = kc * 16 + lq * 2;
            qh[kc][0] = *(const uint32_t*)(a_qi2 + r0o + cA);
            qh[kc][1] = *(const uint32_t*)(a_qi2 + r1o + cA);
            qh[kc][2] = *(const uint32_t*)(a_qi2 + r0o + cA + 8);
            qh[kc][3] = *(const uint32_t*)(a_qi2 + r1o + cA + 8);
        }
    }

    const uint32_t lko = (uint32_t)((((lane >> 3) & 1) * 8 + (lane & 7)) * ASTR * 2
                                    + (lane >> 4) * 16);
    const uint32_t bK = smem_u32(sK), bV = smem_u32(sV);

    float o[8][4];
#pragma unroll
    for (int j = 0; j < 8; j++)
#pragma unroll
        for (int e = 0; e < 4; e++) o[j][e] = 0.f;
    float l0 = 0.f, l1 = 0.f;

    // tile loads: 2 threads per row, 32-elem (64B) halves
    const int trow = tid >> 1;
    const int tcol = (tid & 1) * 32;
    const uint32_t sof = (uint32_t)(trow * ASTR + tcol) * 2;

#pragma unroll 1
    for (int kv = 0; kv < kS; kv += 64) {
        {
            const size_t gofs = head_kv + (size_t)(kv + trow) * kE + tcol;
#pragma unroll
            for (int c = 0; c < 4; c++) {
                *(uint4*)((char*)sK + sof + c * 16) = *(const uint4*)(a_ki2 + gofs + c * 8);
                *(uint4*)((char*)sV + sof + c * 16) = *(const uint4*)(a_vi2 + gofs + c * 8);
            }
        }
        __syncthreads();

        // ---- QK (single pass) ----
        float acc[8][4];
#pragma unroll
        for (int j = 0; j < 8; j++)
#pragma unroll
            for (int e = 0; e < 4; e++) acc[j][e] = 0.f;

#pragma unroll
        for (int kc = 0; kc < 4; kc++) {
            uint32_t kb[8][2];
#pragma unroll
            for (int u = 0; u < 4; u++) {
                uint32_t r0, r1, r2, r3;
                ldsm4(r0, r1, r2, r3, bK + (uint32_t)(u * 16 * ASTR + kc * 16) * 2 + lko);
                kb[2 * u][0] = r0; kb[2 * u][1] = r2;
                kb[2 * u + 1][0] = r1; kb[2 * u + 1][1] = r3;
            }
#pragma unroll
            for (int j = 0; j < 8; j++) mma_f16(acc[j], qh[kc], kb[j]);
        }

        // ---- fixed-offset softmax: p = 2^(s-4); offset cancels in norm ----
        uint32_t pha[4][4], pla[4][4];
#pragma unroll
        for (int j = 0; j < 8; j++) {
            const float p0 = exp2f(acc[j][0] - 4.0f);
            const float p1 = exp2f(acc[j][1] - 4.0f);
            const float p2 = exp2f(acc[j][2] - 4.0f);
            const float p3 = exp2f(acc[j][3] - 4.0f);
            l0 += p0 + p1; l1 += p2 + p3;
            __half h0, e0, h1, e1, h2, e2, h3, e3;
            splith(p0, h0, e0); splith(p1, h1, e1);
            splith(p2, h2, e2); splith(p3, h3, e3);
            const int sc = j >> 1, hh = (j & 1) * 2;
            pha[sc][hh + 0] = pkh(h0, h1); pha[sc][hh + 1] = pkh(h2, h3);
            pla[sc][hh + 0] = pkh(e0, e1); pla[sc][hh + 1] = pkh(e2, e3);
        }

        // ---- PV: (Ph + Pl) . Vh ----
#pragma unroll
        for (int sc = 0; sc < 4; sc++) {
            uint32_t vb[8][2];
#pragma unroll
            for (int u = 0; u < 4; u++) {
                uint32_t r0, r1, r2, r3;
                ldsm4t(r0, r1, r2, r3, bV + (uint32_t)(sc * 16 * ASTR + u * 16) * 2 + lko);
                vb[2 * u][0] = r0; vb[2 * u][1] = r1;
                vb[2 * u + 1][0] = r2; vb[2 * u + 1][1] = r3;
            }
#pragma unroll
            for (int j = 0; j < 8; j++) mma_f16(o[j], pha[sc], vb[j]);
#pragma unroll
            for (int j = 0; j < 8; j++) mma_f16(o[j], pla[sc], vb[j]);
        }
        __syncthreads();
    }

    // ---- epilogue: normalize, bf16 hi/lo split, write a_c ----
    l0 += __shfl_xor_sync(0xffffffffu, l0, 1);
    l0 += __shfl_xor_sync(0xffffffffu, l0, 2);
    l1 += __shfl_xor_sync(0xffffffffu, l1, 1);
    l1 += __shfl_xor_sync(0xffffffffu, l1, 2);
    const float inv0 = 1.0f / l0, inv1 = 1.0f / l1;
    const size_t r0o = head_q + (size_t)(q0 + wid * 16 + lr) * kE;
    const size_t r1o = r0o + 8 * kE;
#pragma unroll
    for (int j = 0; j < 8; j++) {
        const int col = j * 8 + lq * 2;
        __nv_bfloat16 h0, e0, h1, e1;
        split1(o[j][0] * inv0, h0, e0); split1(o[j][1] * inv0, h1, e1);
        *(uint32_t*)(a_c_h + r0o + col) = pk(h0, h1);
        *(uint32_t*)(a_c_l + r0o + col) = pk(e0, e1);
        split1(o[j][2] * inv1, h0, e0); split1(o[j][3] * inv1, h1, e1);
        *(uint32_t*)(a_c_h + r1o + col) = pk(h0, h1);
        *(uint32_t*)(a_c_l + r1o + col) = pk(e0, e1);
    }
}

// ---------------- launch ----------------------------------------------------
extern "C" void kernel_launch(void* const* d_in, const int* in_sizes, int n_in,
                              void* d_out, int out_size) {
    const float* query = (const float*)d_in[0];
    const float* key   = (const float*)d_in[1];
    const float* value = (const float*)d_in[2];
    const float* Wqg   = (const float*)d_in[3];
    const float* bqg   = (const float*)d_in[4];
    const float* Wk    = (const float*)d_in[5];
    const float* bk    = (const float*)d_in[6];
    const float* Wv    = (const float*)d_in[7];
    const float* bv    = (const float*)d_in[8];
    const float* Wq_in = (const float*)d_in[9];
    const float* bq_in = (const float*)d_in[10];
    const float* Wk_in = (const float*)d_in[11];
    const float* bk_in = (const float*)d_in[12];
    const float* Wv_in = (const float*)d_in[13];
    const float* bv_in = (const float*)d_in[14];
    const float* Wout  = (const float*)d_in[15];
    const float* bout  = (const float*)d_in[16];

#define SYM(p, s) void* p; cudaGetSymbolAddress(&p, s)
    SYM(p_cq_h, c_q_h); SYM(p_cq_l, c_q_l);
    SYM(p_ck_h, c_k_h); SYM(p_ck_l, c_k_l);
    SYM(p_cv_h, c_v_h); SYM(p_cv_l, c_v_l);
    SYM(p_aq_h, a_q_h); SYM(p_aq_l, a_q_l);
    SYM(p_ak_h, a_k_h); SYM(p_ak_l, a_k_l);
    SYM(p_ax_h, a_x_h); SYM(p_ax_l, a_x_l);
    SYM(p_qi2, a_qi2); SYM(p_ki2, a_ki2); SYM(p_vi2, a_vi2);
    SYM(p_ac_h, a_c_h); SYM(p_ac_l, a_c_l);
    SYM(p_w0_h, w0_h);  SYM(p_w0_l, w0_l);
    SYM(p_w1_h, w1_h);  SYM(p_w1_l, w1_l);
    SYM(p_w2_h, w2_h);  SYM(p_w2_l, w2_l);
    SYM(p_wq_h, wq_h);  SYM(p_wq_l, wq_l);
    SYM(p_wk_h, wk_h);  SYM(p_wk_l, wk_l);
    SYM(p_wv_h, wv_h);  SYM(p_wv_l, wv_l);
    SYM(p_wo_h, wo_h);  SYM(p_wo_l, wo_l);
#undef SYM

    cudaFuncSetAttribute(gemm_any, cudaFuncAttributeMaxDynamicSharedMemorySize, kSmemGemm);

    typedef const __nv_bfloat16* BP;
    typedef const float4* F4;
    typedef uint2* U2;

    // hi/lo conversions
    cvt_hl3<<<dim3(kNSE / 4 / 256, 3), 256>>>(
        (F4)query, (U2)p_cq_h, (U2)p_cq_l,
        (F4)key,   (U2)p_ck_h, (U2)p_ck_l,
        (F4)value, (U2)p_cv_h, (U2)p_cv_l, kNSE / 4);
    cvt_hl3<<<dim3(kEE / 4 / 256, 3), 256>>>(
        (F4)Wqg, (U2)p_w0_h, (U2)p_w0_l,
        (F4)Wk,  (U2)p_w1_h, (U2)p_w1_l,
        (F4)Wv,  (U2)p_w2_h, (U2)p_w2_l, kEE / 4);
    cvt_hl3<<<dim3(kGEE / 4 / 256, 3), 256>>>(
        (F4)Wq_in, (U2)p_wq_h, (U2)p_wq_l,
        (F4)Wk_in, (U2)p_wk_h, (U2)p_wk_l,
        (F4)Wv_in, (U2)p_wv_h, (U2)p_wv_l, kGEE / 4);
    cvt_hl<<<kGEE / 4 / 256, 256>>>((F4)Wout, (U2)p_wo_h, (U2)p_wo_l, kGEE / 4);

    const float kQScale = 0.125f * 1.44269504f;   // 1/sqrt(D) * log2(e)
    auto mkjob = [](const void* Ah, const void* Al, const void* Wh, const void* Wl,
                    const float* bias, void* o0, void* o1,
                    float scale, int mode, int otype, int mblocks) {
        Job j;
        j.Ah = (BP)Ah; j.Al = (BP)Al; j.Wh = (BP)Wh; j.Wl = (BP)Wl;
        j.bias = bias; j.o0 = o0; j.o1 = o1;
        j.scale = scale; j.mode = mode; j.otype = otype; j.mblocks = mblocks;
        return j;
    };

    // launch 1: outer projections q|k|v  (grid.y 96)
    Jobs3 outer;
    outer.j[0] = mkjob(p_cq_h, p_cq_l, p_w0_h, p_w0_l, bqg, p_aq_h, p_aq_l,
                       1.0f, 0, 1, 32);
    outer.j[1] = mkjob(p_ck_h, p_ck_l, p_w1_h, p_w1_l, bk, p_ak_h, p_ak_l,
                       1.0f, 0, 1, 32);
    outer.j[2] = mkjob(p_cv_h, p_cv_l, p_w2_h, p_w2_l, bv, p_ax_h, p_ax_l,
                       1.0f, 0, 1, 32);
    gemm_any<<<dim3(6, 96), 256, kSmemGemm>>>(outer);

    // launch 2: in-projections qi|ki|vi -> fp16 (grid.y 288)
    Jobs3 inproj;
    inproj.j[0] = mkjob(p_aq_h, p_aq_l, p_wq_h, p_wq_l, bq_in, p_qi2, nullptr,
                        kQScale, 1, 2, 32);
    inproj.j[1] = mkjob(p_ak_h, p_ak_l, p_wk_h, p_wk_l, bk_in, p_ki2, nullptr,
                        1.0f, 2, 2, 128);
    inproj.j[2] = mkjob(p_ax_h, p_ax_l, p_wv_h, p_wv_l, bv_in, p_vi2, nullptr,
                        1.0f, 2, 2, 128);
    gemm_any<<<dim3(6, 288), 256, kSmemGemm>>>(inproj);

    // launch 3: attention
    attn_mma<<<dim3(kT / 64, kB * kG * kH), dim3(128)>>>();

    // launch 4: out-projection (permuted scatter to d_out)
    Jobs3 outp;
    outp.j[0] = mkjob(p_ac_h, p_ac_l, p_wo_h, p_wo_l, bout, d_out, nullptr,
                      1.0f, 3, 0, 32);
    outp.j[1] = outp.j[0]; outp.j[1].mblocks = 0;
    outp.j[2] = outp.j[0]; outp.j[2].mblocks = 0;
    gemm_any<<<dim3(6, 32), 256, kSmemGemm>>>(outp);
}

// round 16
// speedup vs baseline: 1.8029x; 1.2921x over previous
#include <cuda_runtime.h>
#include <cuda_bf16.h>
#include <cuda_fp16.h>
#include <cstdint>

// GroupQueryAttention: B=2, S=2048, E=768, H=12, G=4, D=64, T=512
// Round 16: fp16x2 GEMMs (A fp16 hi/lo, W fp16 single; 2 MMA passes/k16,
// was bf16x3). Error: ~2.4e-4/stage from dropped Ah*Wl; total ~4.6e-4.
// Attention unchanged from r15 (fp16 QKV, fixed-offset base-2 softmax).

constexpr int kE = 768;
constexpr int kB = 2;
constexpr int kS = 2048;
constexpr int kH = 12;
constexpr int kG = 4;
constexpr int kD = 64;
constexpr int kT = 512;                 // S / G
constexpr int kNSE = kB * kS * kE;      // 3,145,728
constexpr int kEE  = kE * kE;           // 589,824
constexpr int kGEE = kG * kE * kE;      // 2,359,296
constexpr int kGSE = kB * kG * kS * kE; // 12,582,912
constexpr int kQTE = kB * kG * kT * kE; // 3,145,728

// ---------------- scratch (device globals; no allocations allowed) ----------
__device__ __half c_q_h[kNSE], c_q_l[kNSE];   // inputs, fp16 hi/lo
__device__ __half c_k_h[kNSE], c_k_l[kNSE];
__device__ __half c_v_h[kNSE], c_v_l[kNSE];
__device__ __half a_q_h[kNSE], a_q_l[kNSE];   // outer projections, fp16 hi/lo
__device__ __half a_k_h[kNSE], a_k_l[kNSE];
__device__ __half a_x_h[kNSE], a_x_l[kNSE];
__device__ __half a_qi2[kQTE];                // fp16 q (pre-scaled)
__device__ __half a_ki2[kGSE];                // fp16 k
__device__ __half a_vi2[kGSE];                // fp16 v
__device__ __half a_c_h[kQTE], a_c_l[kQTE];   // context, fp16 hi/lo
__device__ __half w0[kEE],  w1[kEE],  w2[kEE];       // weights, fp16 single
__device__ __half wq[kGEE], wk[kGEE], wv[kGEE], wo[kGEE];

// ---------------- helpers ----------------------------------------------------
__device__ __forceinline__ uint32_t smem_u32(const void* p) {
    uint32_t a;
    asm("{ .reg .u64 t; cvta.to.shared.u64 t, %1; cvt.u32.u64 %0, t; }"
        : "=r"(a) : "l"(p));
    return a;
}
__device__ __forceinline__ void cp16(uint32_t dst, const void* src) {
    asm volatile("cp.async.cg.shared.global [%0], [%1], 16;" :: "r"(dst), "l"(src));
}
#define CP_COMMIT() asm volatile("cp.async.commit_group;" ::: "memory")
#define CP_WAIT0()  asm volatile("cp.async.wait_group 0;" ::: "memory")

__device__ __forceinline__ void mma_f16(float* c, const uint32_t* a, const uint32_t* b) {
    asm volatile(
        "mma.sync.aligned.m16n8k16.row.col.f32.f16.f16.f32 "
        "{%0,%1,%2,%3}, {%4,%5,%6,%7}, {%8,%9}, {%0,%1,%2,%3};"
        : "+f"(c[0]), "+f"(c[1]), "+f"(c[2]), "+f"(c[3])
        : "r"(a[0]), "r"(a[1]), "r"(a[2]), "r"(a[3]), "r"(b[0]), "r"(b[1]));
}
__device__ __forceinline__ void ldsm4(uint32_t& r0, uint32_t& r1, uint32_t& r2,
                                      uint32_t& r3, uint32_t addr) {
    asm volatile("ldmatrix.sync.aligned.m8n8.x4.shared.b16 {%0,%1,%2,%3}, [%4];"
                 : "=r"(r0), "=r"(r1), "=r"(r2), "=r"(r3) : "r"(addr));
}
__device__ __forceinline__ void ldsm4t(uint32_t& r0, uint32_t& r1, uint32_t& r2,
                                       uint32_t& r3, uint32_t addr) {
    asm volatile("ldmatrix.sync.aligned.m8n8.x4.trans.shared.b16 {%0,%1,%2,%3}, [%4];"
                 : "=r"(r0), "=r"(r1), "=r"(r2), "=r"(r3) : "r"(addr));
}

__device__ __forceinline__ uint32_t pkh(__half a, __half b) {
    uint16_t ua = *(uint16_t*)&a, ub = *(uint16_t*)&b;
    return (uint32_t)ua | ((uint32_t)ub << 16);
}
__device__ __forceinline__ void splith(float x, __half& h, __half& l) {
    h = __float2half_rn(x);
    l = __float2half_rn(x - __half2float(h));
}

// ---------------- row mappings (runtime mode) --------------------------------
__device__ __forceinline__ int in_row_rt(int mode, int m) {
    if (mode == 1) {
        int b = m >> 11; int g = (m >> 9) & 3; int t = m & 511;
        return (b << 11) + (t << 2) + g;
    }
    if (mode == 2) {
        int b = m >> 13; int s = m & 2047;
        return (b << 11) + s;
    }
    return m;
}
__device__ __forceinline__ int perm_row(int m) {
    int b = m >> 11; int g = (m >> 9) & 3; int t = m & 511;
    return (b << 11) + (t << 2) + g;
}

// ---------------- conversion kernels -----------------------------------------
__device__ __forceinline__ void cvt_one_hl(const float4* in, uint2* h, uint2* l, int i) {
    float4 v = in[i];
    __half h0, l0, h1, l1, h2, l2, h3, l3;
    splith(v.x, h0, l0); splith(v.y, h1, l1);
    splith(v.z, h2, l2); splith(v.w, h3, l3);
    h[i] = make_uint2(pkh(h0, h1), pkh(h2, h3));
    l[i] = make_uint2(pkh(l0, l1), pkh(l2, l3));
}
__global__ void cvt_hl3(const float4* __restrict__ i0, uint2* __restrict__ h0, uint2* __restrict__ l0,
                        const float4* __restrict__ i1, uint2* __restrict__ h1, uint2* __restrict__ l1,
                        const float4* __restrict__ i2, uint2* __restrict__ h2, uint2* __restrict__ l2,
                        int n4) {
    int i = blockIdx.x * 256 + threadIdx.x;
    if (i >= n4) return;
    if (blockIdx.y == 0)      cvt_one_hl(i0, h0, l0, i);
    else if (blockIdx.y == 1) cvt_one_hl(i1, h1, l1, i);
    else                      cvt_one_hl(i2, h2, l2, i);
}
__device__ __forceinline__ void cvt_one_h(const float4* in, uint2* h, int i) {
    float4 v = in[i];
    h[i] = make_uint2(pkh(__float2half_rn(v.x), __float2half_rn(v.y)),
                      pkh(__float2half_rn(v.z), __float2half_rn(v.w)));
}
__global__ void cvt_h4(const float4* __restrict__ i0, uint2* __restrict__ h0,
                       const float4* __restrict__ i1, uint2* __restrict__ h1,
                       const float4* __restrict__ i2, uint2* __restrict__ h2,
                       const float4* __restrict__ i3, uint2* __restrict__ h3,
                       int n4) {
    int i = blockIdx.x * 256 + threadIdx.x;
    if (i >= n4) return;
    if (blockIdx.y == 0)      cvt_one_h(i0, h0, i);
    else if (blockIdx.y == 1) cvt_one_h(i1, h1, i);
    else if (blockIdx.y == 2) cvt_one_h(i2, h2, i);
    else                      cvt_one_h(i3, h3, i);
}
__global__ void cvt_h3(const float4* __restrict__ i0, uint2* __restrict__ h0,
                       const float4* __restrict__ i1, uint2* __restrict__ h1,
                       const float4* __restrict__ i2, uint2* __restrict__ h2,
                       int n4) {
    int i = blockIdx.x * 256 + threadIdx.x;
    if (i >= n4) return;
    if (blockIdx.y == 0)      cvt_one_h(i0, h0, i);
    else if (blockIdx.y == 1) cvt_one_h(i1, h1, i);
    else                      cvt_one_h(i2, h2, i);
}

// ---------------- fp16x2 HMMA GEMM, job-table merged -------------------------
// C = gather(A) @ W^T + b;  A = Ah + Al (fp16 pair), W = Wh (fp16 single).
// Per buffer: Ah | Al | Wh  (3 matrices).
constexpr int PSTR = 40;               // padded row stride (fp16 elems)
constexpr int MATB = 128 * PSTR * 2;   // 10240 B per matrix
constexpr int BUFB = 3 * MATB;         // 30720 B per buffer
constexpr int kSmemGemm = 2 * BUFB;    // 61440 B

struct Job {
    const __half *Ah, *Al, *Wh;
    const float* bias;
    void *o0, *o1;          // otype 0: o0=float*; 1: fp16 h,l; 2: fp16 single
    float scale;
    int mode;               // 0 plain / 1 q-gather / 2 kv-broadcast / 3 out-perm
    int otype;
    int mblocks;
};
struct Jobs3 { Job j[3]; };

__global__ __launch_bounds__(256, 2)
void gemm_any(Jobs3 jobs) {
    extern __shared__ char s_raw[];
    const uint32_t sb = smem_u32(s_raw);

    const int tid = threadIdx.x;
    int by = blockIdx.y;
    int ji = 0, jbase = 0;
    if (by >= jobs.j[0].mblocks) {
        jbase = jobs.j[0].mblocks; ji = 1;
        if (by >= jbase + jobs.j[1].mblocks) { jbase += jobs.j[1].mblocks; ji = 2; }
    }
    const Job J = jobs.j[ji];
    const int mode = J.mode;
    const int m0 = (by - jbase) * 128;
    const int n0 = blockIdx.x * 128;

    int g = 0;
    if (mode == 1 || mode == 3) g = (m0 >> 9) & 3;
    if (mode == 2)              g = (m0 >> 11) & 3;
    const __half* WgH = J.Wh + (size_t)g * kEE;
    const float* bg = J.bias + (size_t)g * kE;

    const int lrow = tid >> 1;
    const int lhalf = tid & 1;
    const int arow = in_row_rt(mode, m0 + lrow);
    const __half* pAh = J.Ah + (size_t)arow * kE + lhalf * 16;
    const __half* pAl = J.Al + (size_t)arow * kE + lhalf * 16;
    const __half* pWh = WgH + (size_t)(n0 + lrow) * kE + lhalf * 16;
    const uint32_t sdst = sb + (uint32_t)(lrow * PSTR + lhalf * 16) * 2;

    const int lane = tid & 31;
    const int wid = tid >> 5;
    const int r0 = (wid & 3) * 32;
    const int c0 = (wid >> 2) * 64;
    const int lr = lane >> 2;
    const int lq = lane & 3;

    const uint32_t lmo = (uint32_t)((lane & 15) * PSTR + (lane >> 4) * 8) * 2;

    float acc[2][8][4];
#pragma unroll
    for (int i = 0; i < 2; i++)
#pragma unroll
        for (int j = 0; j < 8; j++)
#pragma unroll
            for (int q = 0; q < 4; q++) acc[i][j][q] = 0.f;

    {
        cp16(sdst,            pAh); cp16(sdst + 16,            pAh + 8);
        cp16(sdst + MATB,     pAl); cp16(sdst + MATB + 16,     pAl + 8);
        cp16(sdst + 2 * MATB, pWh); cp16(sdst + 2 * MATB + 16, pWh + 8);
        CP_COMMIT();
    }

#pragma unroll 1
    for (int p = 0; p < 24; ++p) {
        CP_WAIT0();
        __syncthreads();
        if (p + 1 < 24) {
            const int go = (p + 1) * 32;
            const uint32_t d = sdst + ((p + 1) & 1) * BUFB;
            cp16(d,            pAh + go); cp16(d + 16,            pAh + go + 8);
            cp16(d + MATB,     pAl + go); cp16(d + MATB + 16,     pAl + go + 8);
            cp16(d + 2 * MATB, pWh + go); cp16(d + 2 * MATB + 16, pWh + go + 8);
            CP_COMMIT();
        }

        const uint32_t bbase = sb + (p & 1) * BUFB;
#pragma unroll
        for (int ks = 0; ks < 2; ++ks) {
            const uint32_t ko = lmo + (uint32_t)(ks * 16) * 2;
            uint32_t AhF[2][4], AlF[2][4], BF[8][2];
#pragma unroll
            for (int i = 0; i < 2; i++) {
                const uint32_t ab = bbase + (uint32_t)((r0 + i * 16) * PSTR) * 2 + ko;
                ldsm4(AhF[i][0], AhF[i][1], AhF[i][2], AhF[i][3], ab);
                ldsm4(AlF[i][0], AlF[i][1], AlF[i][2], AlF[i][3], ab + MATB);
            }
#pragma unroll
            for (int u = 0; u < 4; u++) {
                uint32_t q0, q1, q2, q3;
                ldsm4(q0, q1, q2, q3,
                      bbase + 2 * MATB + (uint32_t)((c0 + u * 16) * PSTR) * 2 + ko);
                BF[2 * u][0] = q0; BF[2 * u][1] = q2;
                BF[2 * u + 1][0] = q1; BF[2 * u + 1][1] = q3;
            }
#pragma unroll
            for (int j = 0; j < 8; j++) {
                mma_f16(acc[0][j], AhF[0], BF[j]);
                mma_f16(acc[1][j], AhF[1], BF[j]);
            }
#pragma unroll
            for (int j = 0; j < 8; j++) {
                mma_f16(acc[0][j], AlF[0], BF[j]);
                mma_f16(acc[1][j], AlF[1], BF[j]);
            }
        }
    }

    // epilogue
#pragma unroll
    for (int i = 0; i < 2; i++) {
#pragma unroll
        for (int half = 0; half < 2; half++) {
            const int m = m0 + r0 + i * 16 + lr + half * 8;
            const size_t orow = (mode == 3) ? (size_t)perm_row(m) : (size_t)m;
#pragma unroll
            for (int j = 0; j < 8; j++) {
                const int col = n0 + c0 + j * 8 + lq * 2;
                const float2 bb = *(const float2*)(bg + col);
                float x0 = acc[i][j][half * 2 + 0] + bb.x;
                float x1 = acc[i][j][half * 2 + 1] + bb.y;
                if (J.otype == 0) {
                    *(float2*)((float*)J.o0 + orow * kE + col) = make_float2(x0, x1);
                } else if (J.otype == 1) {
                    x0 *= J.scale; x1 *= J.scale;
                    __half h0, l0, h1, l1;
                    splith(x0, h0, l0); splith(x1, h1, l1);
                    *(uint32_t*)((__half*)J.o0 + orow * kE + col) = pkh(h0, h1);
                    *(uint32_t*)((__half*)J.o1 + orow * kE + col) = pkh(l0, l1);
                } else {
                    x0 *= J.scale; x1 *= J.scale;
                    *(uint32_t*)((__half*)J.o0 + orow * kE + col) =
                        pkh(__float2half_rn(x0), __float2half_rn(x1));
                }
            }
        }
    }
}

// ---------------- fp16 HMMA flash attention (r15, unchanged) -----------------
constexpr int ASTR = 72;   // smem row stride in fp16 elems

__global__ __launch_bounds__(128, 3)
void attn_mma() {
    __shared__ __align__(16) __half sK[64 * ASTR];
    __shared__ __align__(16) __half sV[64 * ASTR];

    const int tid = threadIdx.x;
    const int wid = tid >> 5;
    const int lane = tid & 31;
    const int lr = lane >> 2;
    const int lq = lane & 3;

    const int y = blockIdx.y;
    const int b = y / (kG * kH);
    const int g = (y / kH) & 3;
    const int h = y % kH;
    const int q0 = blockIdx.x * 64;

    const size_t head_q  = ((size_t)(b * kG + g) * kT) * kE + h * kD;
    const size_t head_kv = ((size_t)(b * kG + g) * kS) * kE + h * kD;

    uint32_t qh[4][4];
    {
        const size_t r0o = head_q + (size_t)(q0 + wid * 16 + lr) * kE;
        const size_t r1o = r0o + 8 * kE;
#pragma unroll
        for (int kc = 0; kc < 4; kc++) {
            const int cA = kc * 16 + lq * 2;
            qh[kc][0] = *(const uint32_t*)(a_qi2 + r0o + cA);
            qh[kc][1] = *(const uint32_t*)(a_qi2 + r1o + cA);
            qh[kc][2] = *(const uint32_t*)(a_qi2 + r0o + cA + 8);
            qh[kc][3] = *(const uint32_t*)(a_qi2 + r1o + cA + 8);
        }
    }

    const uint32_t lko = (uint32_t)((((lane >> 3) & 1) * 8 + (lane & 7)) * ASTR * 2
                                    + (lane >> 4) * 16);
    const uint32_t bK = smem_u32(sK), bV = smem_u32(sV);

    float o[8][4];
#pragma unroll
    for (int j = 0; j < 8; j++)
#pragma unroll
        for (int e = 0; e < 4; e++) o[j][e] = 0.f;
    float l0 = 0.f, l1 = 0.f;

    const int trow = tid >> 1;
    const int tcol = (tid & 1) * 32;
    const uint32_t sof = (uint32_t)(trow * ASTR + tcol) * 2;

#pragma unroll 1
    for (int kv = 0; kv < kS; kv += 64) {
        {
            const size_t gofs = head_kv + (size_t)(kv + trow) * kE + tcol;
#pragma unroll
            for (int c = 0; c < 4; c++) {
                *(uint4*)((char*)sK + sof + c * 16) = *(const uint4*)(a_ki2 + gofs + c * 8);
                *(uint4*)((char*)sV + sof + c * 16) = *(const uint4*)(a_vi2 + gofs + c * 8);
            }
        }
        __syncthreads();

        // ---- QK ----
        float acc[8][4];
#pragma unroll
        for (int j = 0; j < 8; j++)
#pragma unroll
            for (int e = 0; e < 4; e++) acc[j][e] = 0.f;

#pragma unroll
        for (int kc = 0; kc < 4; kc++) {
            uint32_t kb[8][2];
#pragma unroll
            for (int u = 0; u < 4; u++) {
                uint32_t r0, r1, r2, r3;
                ldsm4(r0, r1, r2, r3, bK + (uint32_t)(u * 16 * ASTR + kc * 16) * 2 + lko);
                kb[2 * u][0] = r0; kb[2 * u][1] = r2;
                kb[2 * u + 1][0] = r1; kb[2 * u + 1][1] = r3;
            }
#pragma unroll
            for (int j = 0; j < 8; j++) mma_f16(acc[j], qh[kc], kb[j]);
        }

        // ---- fixed-offset softmax: p = 2^(s-4) ----
        uint32_t pha[4][4], pla[4][4];
#pragma unroll
        for (int j = 0; j < 8; j++) {
            const float p0 = exp2f(acc[j][0] - 4.0f);
            const float p1 = exp2f(acc[j][1] - 4.0f);
            const float p2 = exp2f(acc[j][2] - 4.0f);
            const float p3 = exp2f(acc[j][3] - 4.0f);
            l0 += p0 + p1; l1 += p2 + p3;
            __half h0, e0, h1, e1, h2, e2, h3, e3;
            splith(p0, h0, e0); splith(p1, h1, e1);
            splith(p2, h2, e2); splith(p3, h3, e3);
            const int sc = j >> 1, hh = (j & 1) * 2;
            pha[sc][hh + 0] = pkh(h0, h1); pha[sc][hh + 1] = pkh(h2, h3);
            pla[sc][hh + 0] = pkh(e0, e1); pla[sc][hh + 1] = pkh(e2, e3);
        }

        // ---- PV: (Ph + Pl) . V ----
#pragma unroll
        for (int sc = 0; sc < 4; sc++) {
            uint32_t vb[8][2];
#pragma unroll
            for (int u = 0; u < 4; u++) {
                uint32_t r0, r1, r2, r3;
                ldsm4t(r0, r1, r2, r3, bV + (uint32_t)(sc * 16 * ASTR + u * 16) * 2 + lko);
                vb[2 * u][0] = r0; vb[2 * u][1] = r1;
                vb[2 * u + 1][0] = r2; vb[2 * u + 1][1] = r3;
            }
#pragma unroll
            for (int j = 0; j < 8; j++) mma_f16(o[j], pha[sc], vb[j]);
#pragma unroll
            for (int j = 0; j < 8; j++) mma_f16(o[j], pla[sc], vb[j]);
        }
        __syncthreads();
    }

    // ---- epilogue: normalize, fp16 hi/lo split, write a_c ----
    l0 += __shfl_xor_sync(0xffffffffu, l0, 1);
    l0 += __shfl_xor_sync(0xffffffffu, l0, 2);
    l1 += __shfl_xor_sync(0xffffffffu, l1, 1);
    l1 += __shfl_xor_sync(0xffffffffu, l1, 2);
    const float inv0 = 1.0f / l0, inv1 = 1.0f / l1;
    const size_t r0o = head_q + (size_t)(q0 + wid * 16 + lr) * kE;
    const size_t r1o = r0o + 8 * kE;
#pragma unroll
    for (int j = 0; j < 8; j++) {
        const int col = j * 8 + lq * 2;
        __half h0, e0, h1, e1;
        splith(o[j][0] * inv0, h0, e0); splith(o[j][1] * inv0, h1, e1);
        *(uint32_t*)(a_c_h + r0o + col) = pkh(h0, h1);
        *(uint32_t*)(a_c_l + r0o + col) = pkh(e0, e1);
        splith(o[j][2] * inv1, h0, e0); splith(o[j][3] * inv1, h1, e1);
        *(uint32_t*)(a_c_h + r1o + col) = pkh(h0, h1);
        *(uint32_t*)(a_c_l + r1o + col) = pkh(e0, e1);
    }
}

// ---------------- launch ----------------------------------------------------
extern "C" void kernel_launch(void* const* d_in, const int* in_sizes, int n_in,
                              void* d_out, int out_size) {
    const float* query = (const float*)d_in[0];
    const float* key   = (const float*)d_in[1];
    const float* value = (const float*)d_in[2];
    const float* Wqg   = (const float*)d_in[3];
    const float* bqg   = (const float*)d_in[4];
    const float* Wk    = (const float*)d_in[5];
    const float* bk    = (const float*)d_in[6];
    const float* Wv    = (const float*)d_in[7];
    const float* bv    = (const float*)d_in[8];
    const float* Wq_in = (const float*)d_in[9];
    const float* bq_in = (const float*)d_in[10];
    const float* Wk_in = (const float*)d_in[11];
    const float* bk_in = (const float*)d_in[12];
    const float* Wv_in = (const float*)d_in[13];
    const float* bv_in = (const float*)d_in[14];
    const float* Wout  = (const float*)d_in[15];
    const float* bout  = (const float*)d_in[16];

#define SYM(p, s) void* p; cudaGetSymbolAddress(&p, s)
    SYM(p_cq_h, c_q_h); SYM(p_cq_l, c_q_l);
    SYM(p_ck_h, c_k_h); SYM(p_ck_l, c_k_l);
    SYM(p_cv_h, c_v_h); SYM(p_cv_l, c_v_l);
    SYM(p_aq_h, a_q_h); SYM(p_aq_l, a_q_l);
    SYM(p_ak_h, a_k_h); SYM(p_ak_l, a_k_l);
    SYM(p_ax_h, a_x_h); SYM(p_ax_l, a_x_l);
    SYM(p_qi2, a_qi2); SYM(p_ki2, a_ki2); SYM(p_vi2, a_vi2);
    SYM(p_ac_h, a_c_h); SYM(p_ac_l, a_c_l);
    SYM(p_w0, w0); SYM(p_w1, w1); SYM(p_w2, w2);
    SYM(p_wq, wq); SYM(p_wk, wk); SYM(p_wv, wv); SYM(p_wo, wo);
#undef SYM

    cudaFuncSetAttribute(gemm_any, cudaFuncAttributeMaxDynamicSharedMemorySize, kSmemGemm);

    typedef const __half* HP;
    typedef const float4* F4;
    typedef uint2* U2;

    // conversions: inputs -> fp16 hi/lo; weights -> fp16 single
    cvt_hl3<<<dim3(kNSE / 4 / 256, 3), 256>>>(
        (F4)query, (U2)p_cq_h, (U2)p_cq_l,
        (F4)key,   (U2)p_ck_h, (U2)p_ck_l,
        (F4)value, (U2)p_cv_h, (U2)p_cv_l, kNSE / 4);
    cvt_h3<<<dim3(kEE / 4 / 256, 3), 256>>>(
        (F4)Wqg, (U2)p_w0, (F4)Wk, (U2)p_w1, (F4)Wv, (U2)p_w2, kEE / 4);
    cvt_h4<<<dim3(kGEE / 4 / 256, 4), 256>>>(
        (F4)Wq_in, (U2)p_wq, (F4)Wk_in, (U2)p_wk,
        (F4)Wv_in, (U2)p_wv, (F4)Wout,  (U2)p_wo, kGEE / 4);

    const float kQScale = 0.125f * 1.44269504f;   // 1/sqrt(D) * log2(e)
    auto mkjob = [](const void* Ah, const void* Al, const void* Wh,
                    const float* bias, void* o0, void* o1,
                    float scale, int mode, int otype, int mblocks) {
        Job j;
        j.Ah = (HP)Ah; j.Al = (HP)Al; j.Wh = (HP)Wh;
        j.bias = bias; j.o0 = o0; j.o1 = o1;
        j.scale = scale; j.mode = mode; j.otype = otype; j.mblocks = mblocks;
        return j;
    };

    // launch 1: outer projections q|k|v  (grid.y 96)
    Jobs3 outer;
    outer.j[0] = mkjob(p_cq_h, p_cq_l, p_w0, bqg, p_aq_h, p_aq_l, 1.0f, 0, 1, 32);
    outer.j[1] = mkjob(p_ck_h, p_ck_l, p_w1, bk,  p_ak_h, p_ak_l, 1.0f, 0, 1, 32);
    outer.j[2] = mkjob(p_cv_h, p_cv_l, p_w2, bv,  p_ax_h, p_ax_l, 1.0f, 0, 1, 32);
    gemm_any<<<dim3(6, 96), 256, kSmemGemm>>>(outer);

    // launch 2: in-projections qi|ki|vi -> fp16 single (grid.y 288)
    Jobs3 inproj;
    inproj.j[0] = mkjob(p_aq_h, p_aq_l, p_wq, bq_in, p_qi2, nullptr, kQScale, 1, 2, 32);
    inproj.j[1] = mkjob(p_ak_h, p_ak_l, p_wk, bk_in, p_ki2, nullptr, 1.0f, 2, 2, 128);
    inproj.j[2] = mkjob(p_ax_h, p_ax_l, p_wv, bv_in, p_vi2, nullptr, 1.0f, 2, 2, 128);
    gemm_any<<<dim3(6, 288), 256, kSmemGemm>>>(inproj);

    // launch 3: attention
    attn_mma<<<dim3(kT / 64, kB * kG * kH), dim3(128)>>>();

    // launch 4: out-projection (permuted scatter to d_out)
    Jobs3 outp;
    outp.j[0] = mkjob(p_ac_h, p_ac_l, p_wo, bout, d_out, nullptr, 1.0f, 3, 0, 32);
    outp.j[1] = outp.j[0]; outp.j[1].mblocks = 0;
    outp.j[2] = outp.j[0]; outp.j[2].mblocks = 0;
    gemm_any<<<dim3(6, 32), 256, kSmemGemm>>>(outp);
}

// round 17
// speedup vs baseline: 2.5851x; 1.4339x over previous
#include <cuda_runtime.h>
#include <cuda_fp16.h>
#include <cstdint>

// GroupQueryAttention: B=2, S=2048, E=768, H=12, G=4, D=64, T=512
// Round 17: 1-pass fp16 GEMMs (A single x W single). All intermediates fp16
// single. Attention: r15 core (fp16 QKV, P 2-pass, fixed-offset base-2
// softmax), epilogue writes fp16 single context.
// Error model (calibrated): ~6.3e-4 expected vs 1e-3 gate.

constexpr int kE = 768;
constexpr int kB = 2;
constexpr int kS = 2048;
constexpr int kH = 12;
constexpr int kG = 4;
constexpr int kD = 64;
constexpr int kT = 512;                 // S / G
constexpr int kNSE = kB * kS * kE;      // 3,145,728
constexpr int kEE  = kE * kE;           // 589,824
constexpr int kGEE = kG * kE * kE;      // 2,359,296
constexpr int kGSE = kB * kG * kS * kE; // 12,582,912
constexpr int kQTE = kB * kG * kT * kE; // 3,145,728

// ---------------- scratch (device globals; no allocations allowed) ----------
__device__ __half c_q2[kNSE], c_k2[kNSE], c_v2[kNSE];   // inputs fp16
__device__ __half a_q2[kNSE], a_k2[kNSE], a_x2[kNSE];   // outer projections
__device__ __half a_qi2[kQTE];                          // q in-proj (pre-scaled)
__device__ __half a_ki2[kGSE];
__device__ __half a_vi2[kGSE];
__device__ __half a_c2[kQTE];                           // attention context
__device__ __half w0[kEE],  w1[kEE],  w2[kEE];          // weights fp16
__device__ __half wq[kGEE], wk[kGEE], wv[kGEE], wo[kGEE];

// ---------------- helpers ----------------------------------------------------
__device__ __forceinline__ uint32_t smem_u32(const void* p) {
    uint32_t a;
    asm("{ .reg .u64 t; cvta.to.shared.u64 t, %1; cvt.u32.u64 %0, t; }"
        : "=r"(a) : "l"(p));
    return a;
}
__device__ __forceinline__ void cp16(uint32_t dst, const void* src) {
    asm volatile("cp.async.cg.shared.global [%0], [%1], 16;" :: "r"(dst), "l"(src));
}
#define CP_COMMIT() asm volatile("cp.async.commit_group;" ::: "memory")
#define CP_WAIT0()  asm volatile("cp.async.wait_group 0;" ::: "memory")

__device__ __forceinline__ void mma_f16(float* c, const uint32_t* a, const uint32_t* b) {
    asm volatile(
        "mma.sync.aligned.m16n8k16.row.col.f32.f16.f16.f32 "
        "{%0,%1,%2,%3}, {%4,%5,%6,%7}, {%8,%9}, {%0,%1,%2,%3};"
        : "+f"(c[0]), "+f"(c[1]), "+f"(c[2]), "+f"(c[3])
        : "r"(a[0]), "r"(a[1]), "r"(a[2]), "r"(a[3]), "r"(b[0]), "r"(b[1]));
}
__device__ __forceinline__ void ldsm4(uint32_t& r0, uint32_t& r1, uint32_t& r2,
                                      uint32_t& r3, uint32_t addr) {
    asm volatile("ldmatrix.sync.aligned.m8n8.x4.shared.b16 {%0,%1,%2,%3}, [%4];"
                 : "=r"(r0), "=r"(r1), "=r"(r2), "=r"(r3) : "r"(addr));
}
__device__ __forceinline__ void ldsm4t(uint32_t& r0, uint32_t& r1, uint32_t& r2,
                                       uint32_t& r3, uint32_t addr) {
    asm volatile("ldmatrix.sync.aligned.m8n8.x4.trans.shared.b16 {%0,%1,%2,%3}, [%4];"
                 : "=r"(r0), "=r"(r1), "=r"(r2), "=r"(r3) : "r"(addr));
}

__device__ __forceinline__ uint32_t pkh(__half a, __half b) {
    uint16_t ua = *(uint16_t*)&a, ub = *(uint16_t*)&b;
    return (uint32_t)ua | ((uint32_t)ub << 16);
}
__device__ __forceinline__ void splith(float x, __half& h, __half& l) {
    h = __float2half_rn(x);
    l = __float2half_rn(x - __half2float(h));
}

// ---------------- row mappings (runtime mode) --------------------------------
__device__ __forceinline__ int in_row_rt(int mode, int m) {
    if (mode == 1) {
        int b = m >> 11; int g = (m >> 9) & 3; int t = m & 511;
        return (b << 11) + (t << 2) + g;
    }
    if (mode == 2) {
        int b = m >> 13; int s = m & 2047;
        return (b << 11) + s;
    }
    return m;
}
__device__ __forceinline__ int perm_row(int m) {
    int b = m >> 11; int g = (m >> 9) & 3; int t = m & 511;
    return (b << 11) + (t << 2) + g;
}

// ---------------- conversion kernels (fp32 -> fp16 single) -------------------
__device__ __forceinline__ void cvt_one_h(const float4* in, uint2* h, int i) {
    float4 v = in[i];
    h[i] = make_uint2(pkh(__float2half_rn(v.x), __float2half_rn(v.y)),
                      pkh(__float2half_rn(v.z), __float2half_rn(v.w)));
}
__global__ void cvt_h3(const float4* __restrict__ i0, uint2* __restrict__ h0,
                       const float4* __restrict__ i1, uint2* __restrict__ h1,
                       const float4* __restrict__ i2, uint2* __restrict__ h2,
                       int n4) {
    int i = blockIdx.x * 256 + threadIdx.x;
    if (i >= n4) return;
    if (blockIdx.y == 0)      cvt_one_h(i0, h0, i);
    else if (blockIdx.y == 1) cvt_one_h(i1, h1, i);
    else                      cvt_one_h(i2, h2, i);
}
__global__ void cvt_h4(const float4* __restrict__ i0, uint2* __restrict__ h0,
                       const float4* __restrict__ i1, uint2* __restrict__ h1,
                       const float4* __restrict__ i2, uint2* __restrict__ h2,
                       const float4* __restrict__ i3, uint2* __restrict__ h3,
                       int n4) {
    int i = blockIdx.x * 256 + threadIdx.x;
    if (i >= n4) return;
    if (blockIdx.y == 0)      cvt_one_h(i0, h0, i);
    else if (blockIdx.y == 1) cvt_one_h(i1, h1, i);
    else if (blockIdx.y == 2) cvt_one_h(i2, h2, i);
    else                      cvt_one_h(i3, h3, i);
}

// ---------------- 1-pass fp16 HMMA GEMM, job-table merged --------------------
// C = gather(A) @ W^T + b; A, W fp16 single. Buffer: A | W (2 matrices).
constexpr int PSTR = 40;               // padded row stride (fp16 elems)
constexpr int MATB = 128 * PSTR * 2;   // 10240 B per matrix
constexpr int BUFB = 2 * MATB;         // 20480 B per buffer
constexpr int kSmemGemm = 2 * BUFB;    // 40960 B

struct Job {
    const __half *Ah, *Wh;
    const float* bias;
    void* o0;               // otype 0: float*, 2: __half*
    float scale;
    int mode;               // 0 plain / 1 q-gather / 2 kv-broadcast / 3 out-perm
    int otype;              // 0 fp32 / 2 fp16 single
    int mblocks;
};
struct Jobs3 { Job j[3]; };

__global__ __launch_bounds__(256, 2)
void gemm_any(Jobs3 jobs) {
    extern __shared__ char s_raw[];
    const uint32_t sb = smem_u32(s_raw);

    const int tid = threadIdx.x;
    int by = blockIdx.y;
    int ji = 0, jbase = 0;
    if (by >= jobs.j[0].mblocks) {
        jbase = jobs.j[0].mblocks; ji = 1;
        if (by >= jbase + jobs.j[1].mblocks) { jbase += jobs.j[1].mblocks; ji = 2; }
    }
    const Job J = jobs.j[ji];
    const int mode = J.mode;
    const int m0 = (by - jbase) * 128;
    const int n0 = blockIdx.x * 128;

    int g = 0;
    if (mode == 1 || mode == 3) g = (m0 >> 9) & 3;
    if (mode == 2)              g = (m0 >> 11) & 3;
    const __half* WgH = J.Wh + (size_t)g * kEE;
    const float* bg = J.bias + (size_t)g * kE;

    const int lrow = tid >> 1;
    const int lhalf = tid & 1;
    const int arow = in_row_rt(mode, m0 + lrow);
    const __half* pAh = J.Ah + (size_t)arow * kE + lhalf * 16;
    const __half* pWh = WgH + (size_t)(n0 + lrow) * kE + lhalf * 16;
    const uint32_t sdst = sb + (uint32_t)(lrow * PSTR + lhalf * 16) * 2;

    const int lane = tid & 31;
    const int wid = tid >> 5;
    const int r0 = (wid & 3) * 32;
    const int c0 = (wid >> 2) * 64;
    const int lr = lane >> 2;
    const int lq = lane & 3;

    const uint32_t lmo = (uint32_t)((lane & 15) * PSTR + (lane >> 4) * 8) * 2;

    float acc[2][8][4];
#pragma unroll
    for (int i = 0; i < 2; i++)
#pragma unroll
        for (int j = 0; j < 8; j++)
#pragma unroll
            for (int q = 0; q < 4; q++) acc[i][j][q] = 0.f;

    {
        cp16(sdst,        pAh); cp16(sdst + 16,        pAh + 8);
        cp16(sdst + MATB, pWh); cp16(sdst + MATB + 16, pWh + 8);
        CP_COMMIT();
    }

#pragma unroll 1
    for (int p = 0; p < 24; ++p) {
        CP_WAIT0();
        __syncthreads();
        if (p + 1 < 24) {
            const int go = (p + 1) * 32;
            const uint32_t d = sdst + ((p + 1) & 1) * BUFB;
            cp16(d,        pAh + go); cp16(d + 16,        pAh + go + 8);
            cp16(d + MATB, pWh + go); cp16(d + MATB + 16, pWh + go + 8);
            CP_COMMIT();
        }

        const uint32_t bbase = sb + (p & 1) * BUFB;
#pragma unroll
        for (int ks = 0; ks < 2; ++ks) {
            const uint32_t ko = lmo + (uint32_t)(ks * 16) * 2;
            uint32_t AhF[2][4], BF[8][2];
#pragma unroll
            for (int i = 0; i < 2; i++) {
                const uint32_t ab = bbase + (uint32_t)((r0 + i * 16) * PSTR) * 2 + ko;
                ldsm4(AhF[i][0], AhF[i][1], AhF[i][2], AhF[i][3], ab);
            }
#pragma unroll
            for (int u = 0; u < 4; u++) {
                uint32_t q0, q1, q2, q3;
                ldsm4(q0, q1, q2, q3,
                      bbase + MATB + (uint32_t)((c0 + u * 16) * PSTR) * 2 + ko);
                BF[2 * u][0] = q0; BF[2 * u][1] = q2;
                BF[2 * u + 1][0] = q1; BF[2 * u + 1][1] = q3;
            }
#pragma unroll
            for (int j = 0; j < 8; j++) {
                mma_f16(acc[0][j], AhF[0], BF[j]);
                mma_f16(acc[1][j], AhF[1], BF[j]);
            }
        }
    }

    // epilogue
#pragma unroll
    for (int i = 0; i < 2; i++) {
#pragma unroll
        for (int half = 0; half < 2; half++) {
            const int m = m0 + r0 + i * 16 + lr + half * 8;
            const size_t orow = (mode == 3) ? (size_t)perm_row(m) : (size_t)m;
#pragma unroll
            for (int j = 0; j < 8; j++) {
                const int col = n0 + c0 + j * 8 + lq * 2;
                const float2 bb = *(const float2*)(bg + col);
                float x0 = acc[i][j][half * 2 + 0] + bb.x;
                float x1 = acc[i][j][half * 2 + 1] + bb.y;
                if (J.otype == 0) {
                    *(float2*)((float*)J.o0 + orow * kE + col) = make_float2(x0, x1);
                } else {
                    x0 *= J.scale; x1 *= J.scale;
                    *(uint32_t*)((__half*)J.o0 + orow * kE + col) =
                        pkh(__float2half_rn(x0), __float2half_rn(x1));
                }
            }
        }
    }
}

// ---------------- fp16 HMMA flash attention ----------------------------------
// r15 core: fp16 QKV single, P 2-pass fp16, fixed-offset base-2 softmax.
// Epilogue writes fp16 single context.
constexpr int ASTR = 72;   // smem row stride in fp16 elems

__global__ __launch_bounds__(128, 3)
void attn_mma() {
    __shared__ __align__(16) __half sK[64 * ASTR];
    __shared__ __align__(16) __half sV[64 * ASTR];

    const int tid = threadIdx.x;
    const int wid = tid >> 5;
    const int lane = tid & 31;
    const int lr = lane >> 2;
    const int lq = lane & 3;

    const int y = blockIdx.y;
    const int b = y / (kG * kH);
    const int g = (y / kH) & 3;
    const int h = y % kH;
    const int q0 = blockIdx.x * 64;

    const size_t head_q  = ((size_t)(b * kG + g) * kT) * kE + h * kD;
    const size_t head_kv = ((size_t)(b * kG + g) * kS) * kE + h * kD;

    uint32_t qh[4][4];
    {
        const size_t r0o = head_q + (size_t)(q0 + wid * 16 + lr) * kE;
        const size_t r1o = r0o + 8 * kE;
#pragma unroll
        for (int kc = 0; kc < 4; kc++) {
            const int cA = kc * 16 + lq * 2;
            qh[kc][0] = *(const uint32_t*)(a_qi2 + r0o + cA);
            qh[kc][1] = *(const uint32_t*)(a_qi2 + r1o + cA);
            qh[kc][2] = *(const uint32_t*)(a_qi2 + r0o + cA + 8);
            qh[kc][3] = *(const uint32_t*)(a_qi2 + r1o + cA + 8);
        }
    }

    const uint32_t lko = (uint32_t)((((lane >> 3) & 1) * 8 + (lane & 7)) * ASTR * 2
                                    + (lane >> 4) * 16);
    const uint32_t bK = smem_u32(sK), bV = smem_u32(sV);

    float o[8][4];
#pragma unroll
    for (int j = 0; j < 8; j++)
#pragma unroll
        for (int e = 0; e < 4; e++) o[j][e] = 0.f;
    float l0 = 0.f, l1 = 0.f;

    const int trow = tid >> 1;
    const int tcol = (tid & 1) * 32;
    const uint32_t sof = (uint32_t)(trow * ASTR + tcol) * 2;

#pragma unroll 1
    for (int kv = 0; kv < kS; kv += 64) {
        {
            const size_t gofs = head_kv + (size_t)(kv + trow) * kE + tcol;
#pragma unroll
            for (int c = 0; c < 4; c++) {
                *(uint4*)((char*)sK + sof + c * 16) = *(const uint4*)(a_ki2 + gofs + c * 8);
                *(uint4*)((char*)sV + sof + c * 16) = *(const uint4*)(a_vi2 + gofs + c * 8);
            }
        }
        __syncthreads();

        // ---- QK ----
        float acc[8][4];
#pragma unroll
        for (int j = 0; j < 8; j++)
#pragma unroll
            for (int e = 0; e < 4; e++) acc[j][e] = 0.f;

#pragma unroll
        for (int kc = 0; kc < 4; kc++) {
            uint32_t kb[8][2];
#pragma unroll
            for (int u = 0; u < 4; u++) {
                uint32_t r0, r1, r2, r3;
                ldsm4(r0, r1, r2, r3, bK + (uint32_t)(u * 16 * ASTR + kc * 16) * 2 + lko);
                kb[2 * u][0] = r0; kb[2 * u][1] = r2;
                kb[2 * u + 1][0] = r1; kb[2 * u + 1][1] = r3;
            }
#pragma unroll
            for (int j = 0; j < 8; j++) mma_f16(acc[j], qh[kc], kb[j]);
        }

        // ---- fixed-offset softmax: p = 2^(s-4); offset cancels in norm ----
        uint32_t pha[4][4], pla[4][4];
#pragma unroll
        for (int j = 0; j < 8; j++) {
            const float p0 = exp2f(acc[j][0] - 4.0f);
            const float p1 = exp2f(acc[j][1] - 4.0f);
            const float p2 = exp2f(acc[j][2] - 4.0f);
            const float p3 = exp2f(acc[j][3] - 4.0f);
            l0 += p0 + p1; l1 += p2 + p3;
            __half h0, e0, h1, e1, h2, e2, h3, e3;
            splith(p0, h0, e0); splith(p1, h1, e1);
            splith(p2, h2, e2); splith(p3, h3, e3);
            const int sc = j >> 1, hh = (j & 1) * 2;
            pha[sc][hh + 0] = pkh(h0, h1); pha[sc][hh + 1] = pkh(h2, h3);
            pla[sc][hh + 0] = pkh(e0, e1); pla[sc][hh + 1] = pkh(e2, e3);
        }

        // ---- PV: (Ph + Pl) . V ----
#pragma unroll
        for (int sc = 0; sc < 4; sc++) {
            uint32_t vb[8][2];
#pragma unroll
            for (int u = 0; u < 4; u++) {
                uint32_t r0, r1, r2, r3;
                ldsm4t(r0, r1, r2, r3, bV + (uint32_t)(sc * 16 * ASTR + u * 16) * 2 + lko);
                vb[2 * u][0] = r0; vb[2 * u][1] = r1;
                vb[2 * u + 1][0] = r2; vb[2 * u + 1][1] = r3;
            }
#pragma unroll
            for (int j = 0; j < 8; j++) mma_f16(o[j], pha[sc], vb[j]);
#pragma unroll
            for (int j = 0; j < 8; j++) mma_f16(o[j], pla[sc], vb[j]);
        }
        __syncthreads();
    }

    // ---- epilogue: normalize, write fp16 context ----
    l0 += __shfl_xor_sync(0xffffffffu, l0, 1);
    l0 += __shfl_xor_sync(0xffffffffu, l0, 2);
    l1 += __shfl_xor_sync(0xffffffffu, l1, 1);
    l1 += __shfl_xor_sync(0xffffffffu, l1, 2);
    const float inv0 = 1.0f / l0, inv1 = 1.0f / l1;
    const size_t r0o = head_q + (size_t)(q0 + wid * 16 + lr) * kE;
    const size_t r1o = r0o + 8 * kE;
#pragma unroll
    for (int j = 0; j < 8; j++) {
        const int col = j * 8 + lq * 2;
        *(uint32_t*)(a_c2 + r0o + col) =
            pkh(__float2half_rn(o[j][0] * inv0), __float2half_rn(o[j][1] * inv0));
        *(uint32_t*)(a_c2 + r1o + col) =
            pkh(__float2half_rn(o[j][2] * inv1), __float2half_rn(o[j][3] * inv1));
    }
}

// ---------------- launch ----------------------------------------------------
extern "C" void kernel_launch(void* const* d_in, const int* in_sizes, int n_in,
                              void* d_out, int out_size) {
    const float* query = (const float*)d_in[0];
    const float* key   = (const float*)d_in[1];
    const float* value = (const float*)d_in[2];
    const float* Wqg   = (const float*)d_in[3];
    const float* bqg   = (const float*)d_in[4];
    const float* Wk    = (const float*)d_in[5];
    const float* bk    = (const float*)d_in[6];
    const float* Wv    = (const float*)d_in[7];
    const float* bv    = (const float*)d_in[8];
    const float* Wq_in = (const float*)d_in[9];
    const float* bq_in = (const float*)d_in[10];
    const float* Wk_in = (const float*)d_in[11];
    const float* bk_in = (const float*)d_in[12];
    const float* Wv_in = (const float*)d_in[13];
    const float* bv_in = (const float*)d_in[14];
    const float* Wout  = (const float*)d_in[15];
    const float* bout  = (const float*)d_in[16];

#define SYM(p, s) void* p; cudaGetSymbolAddress(&p, s)
    SYM(p_cq, c_q2); SYM(p_ck, c_k2); SYM(p_cv, c_v2);
    SYM(p_aq, a_q2); SYM(p_ak, a_k2); SYM(p_ax, a_x2);
    SYM(p_qi, a_qi2); SYM(p_ki, a_ki2); SYM(p_vi, a_vi2);
    SYM(p_ac, a_c2);
    SYM(p_w0, w0); SYM(p_w1, w1); SYM(p_w2, w2);
    SYM(p_wq, wq); SYM(p_wk, wk); SYM(p_wv, wv); SYM(p_wo, wo);
#undef SYM

    cudaFuncSetAttribute(gemm_any, cudaFuncAttributeMaxDynamicSharedMemorySize, kSmemGemm);

    typedef const __half* HP;
    typedef const float4* F4;
    typedef uint2* U2;

    // conversions: everything -> fp16 single
    cvt_h3<<<dim3(kNSE / 4 / 256, 3), 256>>>(
        (F4)query, (U2)p_cq, (F4)key, (U2)p_ck, (F4)value, (U2)p_cv, kNSE / 4);
    cvt_h3<<<dim3(kEE / 4 / 256, 3), 256>>>(
        (F4)Wqg, (U2)p_w0, (F4)Wk, (U2)p_w1, (F4)Wv, (U2)p_w2, kEE / 4);
    cvt_h4<<<dim3(kGEE / 4 / 256, 4), 256>>>(
        (F4)Wq_in, (U2)p_wq, (F4)Wk_in, (U2)p_wk,
        (F4)Wv_in, (U2)p_wv, (F4)Wout,  (U2)p_wo, kGEE / 4);

    const float kQScale = 0.125f * 1.44269504f;   // 1/sqrt(D) * log2(e)
    auto mkjob = [](const void* Ah, const void* Wh, const float* bias, void* o0,
                    float scale, int mode, int otype, int mblocks) {
        Job j;
        j.Ah = (HP)Ah; j.Wh = (HP)Wh; j.bias = bias; j.o0 = o0;
        j.scale = scale; j.mode = mode; j.otype = otype; j.mblocks = mblocks;
        return j;
    };

    // launch 1: outer projections q|k|v  (grid.y 96)
    Jobs3 outer;
    outer.j[0] = mkjob(p_cq, p_w0, bqg, p_aq, 1.0f, 0, 2, 32);
    outer.j[1] = mkjob(p_ck, p_w1, bk,  p_ak, 1.0f, 0, 2, 32);
    outer.j[2] = mkjob(p_cv, p_w2, bv,  p_ax, 1.0f, 0, 2, 32);
    gemm_any<<<dim3(6, 96), 256, kSmemGemm>>>(outer);

    // launch 2: in-projections qi|ki|vi  (grid.y 288)
    Jobs3 inproj;
    inproj.j[0] = mkjob(p_aq, p_wq, bq_in, p_qi, kQScale, 1, 2, 32);
    inproj.j[1] = mkjob(p_ak, p_wk, bk_in, p_ki, 1.0f, 2, 2, 128);
    inproj.j[2] = mkjob(p_ax, p_wv, bv_in, p_vi, 1.0f, 2, 2, 128);
    gemm_any<<<dim3(6, 288), 256, kSmemGemm>>>(inproj);

    // launch 3: attention
    attn_mma<<<dim3(kT / 64, kB * kG * kH), dim3(128)>>>();

    // launch 4: out-projection (permuted scatter to d_out)
    Jobs3 outp;
    outp.j[0] = mkjob(p_ac, p_wo, bout, d_out, 1.0f, 3, 0, 32);
    outp.j[1] = outp.j[0]; outp.j[1].mblocks = 0;
    outp.j[2] = outp.j[0]; outp.j[2].mblocks = 0;
    gemm_any<<<dim3(6, 32), 256, kSmemGemm>>>(outp);
}